// round 13
// baseline (speedup 1.0000x reference)
#include <cuda_runtime.h>
#include <cuda_bf16.h>
#include <cstdint>

#define NN 4096
#define DD 256
#define HH 8
#define DHH 32
#define EE 131072

// ---------------- scratch ----------------
__device__ float g_q[HH * NN * DHH];
__device__ float g_k[HH * NN * DHH];
__device__ float g_v[HH * NN * DHH];
__device__ float g_att[NN * DD];      // unnormalized attn out
__device__ float g_l[HH * NN];        // row sums
__device__ float g_tmp[NN * DD];
// CSR of edges keyed by source row (sorted by dst within row)
__device__ int g_cnt[NN];
__device__ int g_cur[NN];
__device__ int g_off[NN + 1];
__device__ int g_epack[EE];           // dst | (type<<12)
// split-bf16 operands for flash3
__device__ __nv_bfloat16 g_qs[HH * NN * 64];   // per row: [hi 32][lo 32], q pre-scaled
__device__ __nv_bfloat16 g_ks[HH * NN * 64];
__device__ __nv_bfloat16 g_vth[HH * 32 * NN];  // V^T hi  [h][d][n]
__device__ __nv_bfloat16 g_vtl[HH * 32 * NN];  // V^T lo
// split-bf16 operands for projection GEMMs
__device__ __nv_bfloat16 g_hs[NN * 512];       // h=x+pos: row = [hi k256 | lo k256]
__device__ __nv_bfloat16 g_wt[4 * 256 * 512];  // [z][n][hi k256 | lo k256] (transposed W)
__device__ __nv_bfloat16 g_as[NN * 512];       // normalized att splits

// ---------------- flash3 smem layout (dynamic, double-buffered K/V) ----------------
#define OQ    0
#define OKB   18432
#define OVB   55296
#define SM3   90112

__device__ __forceinline__ uint32_t s2u(const void* p) {
    uint32_t a;
    asm("{ .reg .u64 t; cvta.to.shared.u64 t, %1; cvt.u32.u64 %0, t; }" : "=r"(a) : "l"(p));
    return a;
}
__device__ __forceinline__ float mexp(float s) {
    float r;
    asm("ex2.approx.f32 %0, %1;" : "=f"(r) : "f"(s * 1.4426950408889634f));
    return r;
}

#define LDM_X2(r_, a_)                                                         \
    asm volatile("ldmatrix.sync.aligned.m8n8.x2.shared.b16 {%0,%1}, [%2];"     \
                 : "=r"((r_)[0]), "=r"((r_)[1]) : "r"(a_))
#define LDM_X4(r_, a_)                                                         \
    asm volatile("ldmatrix.sync.aligned.m8n8.x4.shared.b16 {%0,%1,%2,%3}, [%4];" \
                 : "=r"((r_)[0]), "=r"((r_)[1]), "=r"((r_)[2]), "=r"((r_)[3]) : "r"(a_))
#define MMA_BF16(c_, a_, b_)                                                   \
    asm volatile("mma.sync.aligned.m16n8k16.row.col.f32.bf16.bf16.f32 "        \
                 "{%0,%1,%2,%3}, {%4,%5,%6,%7}, {%8,%9}, {%0,%1,%2,%3};"       \
                 : "+f"((c_)[0]), "+f"((c_)[1]), "+f"((c_)[2]), "+f"((c_)[3])  \
                 : "r"((a_)[0]), "r"((a_)[1]), "r"((a_)[2]), "r"((a_)[3]),     \
                   "r"((b_)[0]), "r"((b_)[1]))
#define CVT2(d_, hi_, lo_) \
    asm("cvt.rn.bf16x2.f32 %0, %1, %2;" : "=r"(d_) : "f"(hi_), "f"(lo_))
#define CPA16(dst, src) \
    asm volatile("cp.async.ca.shared.global [%0], [%1], 16;" :: "r"(dst), "l"(src))
#define CPA_COMMIT() asm volatile("cp.async.commit_group;" ::: "memory")
#define CPA_WAIT0() asm volatile("cp.async.wait_group 0;" ::: "memory")
#define CPA_WAIT1() asm volatile("cp.async.wait_group 1;" ::: "memory")

// ---------------- 1a. h = x+pos, split to bf16 hi/lo ----------------
__global__ void k_preph(const float* __restrict__ x, const float* __restrict__ pos) {
    int i4 = blockIdx.x * 256 + threadIdx.x;      // float4 over N*D
    int row = i4 >> 6, c = (i4 & 63) * 4;
    float4 a = ((const float4*)x)[i4];
    float4 b = ((const float4*)pos)[i4];
    float v[4] = {a.x + b.x, a.y + b.y, a.z + b.z, a.w + b.w};
    __nv_bfloat16 hi[4], lo[4];
    #pragma unroll
    for (int j = 0; j < 4; j++) {
        hi[j] = __float2bfloat16(v[j]);
        lo[j] = __float2bfloat16(v[j] - __bfloat162float(hi[j]));
    }
    *(uint2*)(g_hs + (size_t)row * 512 + c) = *(uint2*)hi;
    *(uint2*)(g_hs + (size_t)row * 512 + 256 + c) = *(uint2*)lo;
}

// ---------------- 1b. weights: transpose + split ----------------
__global__ void k_prepw(const float* __restrict__ Wq, const float* __restrict__ Wk,
                        const float* __restrict__ Wv, const float* __restrict__ Wo) {
    int idx = blockIdx.x * 256 + threadIdx.x;     // 32768
    int z = idx >> 13, rem = idx & 8191;
    int k = (rem >> 6) * 2, n4 = (rem & 63) * 4;
    const float* W = (z == 0) ? Wq : (z == 1) ? Wk : (z == 2) ? Wv : Wo;
    float4 r0 = *(const float4*)(W + k * 256 + n4);
    float4 r1 = *(const float4*)(W + (k + 1) * 256 + n4);
    float v0[4] = {r0.x, r0.y, r0.z, r0.w};
    float v1[4] = {r1.x, r1.y, r1.z, r1.w};
    #pragma unroll
    for (int j = 0; j < 4; j++) {
        int n = n4 + j;
        __nv_bfloat16 h0 = __float2bfloat16(v0[j]), h1 = __float2bfloat16(v1[j]);
        uint32_t hp, lp;
        CVT2(hp, __bfloat162float(h1) * 0.0f + v1[j], v0[j]);  // pack hi(v1)|hi(v0)
        // (cvt rounds v to bf16 directly)
        CVT2(lp, v1[j] - __bfloat162float(h1), v0[j] - __bfloat162float(h0));
        size_t base = ((size_t)(z * 256 + n)) * 512 + k;
        *(uint32_t*)(g_wt + base) = hp;
        *(uint32_t*)(g_wt + base + 256) = lp;
    }
}

// ---------------- 2. fused QKV projection via mma.sync ----------------
// grid (6, 32): n0g = bx*128 over [q|k|v] concat cols; 256 threads, 8 warps (4 m x 2 n).
__global__ void __launch_bounds__(256, 2) k_qkvmma(
    const float* __restrict__ bq, const float* __restrict__ bk,
    const float* __restrict__ bv) {
    __shared__ __align__(16) char As[128 * 144];
    __shared__ __align__(16) char Bs[128 * 144];
    const uint32_t sa = s2u(As), sbm = s2u(Bs);
    const int tid = threadIdx.x, w = tid >> 5, lane = tid & 31;
    const int g = lane >> 2, c = lane & 3;
    const int m0 = blockIdx.y * 128, n0g = blockIdx.x * 128;
    const int z = n0g >> 8, cb = n0g & 255;
    const int mr = (w & 3) * 32, nc = (w >> 2) * 64;
    const __nv_bfloat16* wt = g_wt + ((size_t)(z * 256 + cb)) * 512;

    float acc[2][8][4];
    #pragma unroll
    for (int mi = 0; mi < 2; mi++)
        #pragma unroll
        for (int nt = 0; nt < 8; nt++)
            #pragma unroll
            for (int i = 0; i < 4; i++) acc[mi][nt][i] = 0.0f;

    for (int ks = 0; ks < 8; ks++) {
        int kk = ks * 32;
        __syncthreads();
        #pragma unroll
        for (int i = tid; i < 1024; i += 256) {
            int r = i >> 3, u = i & 7;
            int go = (u < 4) ? (kk + u * 8) : (256 + kk + (u - 4) * 8);
            *(uint4*)(As + r * 144 + u * 16) =
                *(const uint4*)(g_hs + (size_t)(m0 + r) * 512 + go);
            *(uint4*)(Bs + r * 144 + u * 16) =
                *(const uint4*)(wt + (size_t)r * 512 + go);
        }
        __syncthreads();
        #pragma unroll
        for (int kh = 0; kh < 2; kh++) {
            uint32_t ah[2][4], al[2][4];
            int rr = (lane & 7) + ((lane >> 3) & 1) * 8;
            #pragma unroll
            for (int mi = 0; mi < 2; mi++) {
                uint32_t base = sa + (mr + mi * 16 + rr) * 144 + kh * 32 + (lane >> 4) * 16;
                LDM_X4(ah[mi], base);
                LDM_X4(al[mi], base + 64);
            }
            #pragma unroll
            for (int nt = 0; nt < 8; nt++) {
                uint32_t bh[2], bl[2];
                uint32_t bb = sbm + (nc + nt * 8 + (lane & 7)) * 144 + kh * 32 +
                              ((lane >> 3) & 1) * 16;
                LDM_X2(bh, bb);
                LDM_X2(bl, bb + 64);
                #pragma unroll
                for (int mi = 0; mi < 2; mi++) {
                    MMA_BF16(acc[mi][nt], ah[mi], bh);
                    MMA_BF16(acc[mi][nt], ah[mi], bl);
                    MMA_BF16(acc[mi][nt], al[mi], bh);
                }
            }
        }
    }

    const float* bias = (z == 0) ? bq : (z == 1) ? bk : bv;
    float* outp = (z == 0) ? g_q : (z == 1) ? g_k : g_v;
    __nv_bfloat16* sp = (z == 0) ? g_qs : g_ks;
    const float sc = (z == 0) ? 0.17677669529663687f : 1.0f;
    #pragma unroll
    for (int mi = 0; mi < 2; mi++) {
        int row0 = m0 + mr + mi * 16 + g;
        #pragma unroll
        for (int nt = 0; nt < 8; nt++) {
            int c0 = cb + nc + nt * 8 + 2 * c;
            int h = c0 >> 5, dh = c0 & 31;
            float b0 = bias[c0], b1 = bias[c0 + 1];
            float v00 = acc[mi][nt][0] + b0, v01 = acc[mi][nt][1] + b1;
            float v10 = acc[mi][nt][2] + b0, v11 = acc[mi][nt][3] + b1;
            size_t ob = ((size_t)h * NN + row0) * 32 + dh;
            *(float2*)(outp + ob) = make_float2(v00, v01);
            *(float2*)(outp + ob + 256) = make_float2(v10, v11);
            if (z < 2) {
                float s00 = v00 * sc, s01 = v01 * sc, s10 = v10 * sc, s11 = v11 * sc;
                uint32_t hp0, lp0, hp1, lp1;
                CVT2(hp0, s01, s00);
                CVT2(hp1, s11, s10);
                float r0 = __uint_as_float(hp0 << 16), r1 = __uint_as_float(hp0 & 0xFFFF0000u);
                float r2 = __uint_as_float(hp1 << 16), r3 = __uint_as_float(hp1 & 0xFFFF0000u);
                CVT2(lp0, s01 - r1, s00 - r0);
                CVT2(lp1, s11 - r3, s10 - r2);
                size_t sb2 = ((size_t)h * NN + row0) * 64 + dh;
                *(uint32_t*)(sp + sb2) = hp0;
                *(uint32_t*)(sp + sb2 + 32) = lp0;
                *(uint32_t*)(sp + sb2 + 512) = hp1;
                *(uint32_t*)(sp + sb2 + 512 + 32) = lp1;
            }
        }
    }
}

// ---------------- 3. V^T hi/lo split ----------------
__global__ void k_split_vt() {
    int idx = blockIdx.x * 256 + threadIdx.x;
    int hh2 = idx >> 12, n = idx & 4095;
    const float* src = g_v + (size_t)idx * 32;
    #pragma unroll
    for (int d = 0; d < 32; d++) {
        float v = src[d];
        __nv_bfloat16 hi = __float2bfloat16(v);
        size_t o = (size_t)(hh2 * 32 + d) * NN + n;
        g_vth[o] = hi;
        g_vtl[o] = __float2bfloat16(v - __bfloat162float(hi));
    }
}

// ---------------- 4. CSR build + per-row dst sort ----------------
__global__ void k_zero() {
    int i = blockIdx.x * 256 + threadIdx.x;
    if (i < NN) { g_cnt[i] = 0; g_cur[i] = 0; }
}
__global__ void k_count(const int* __restrict__ ei) {
    int e = blockIdx.x * 256 + threadIdx.x;
    atomicAdd(&g_cnt[ei[e]], 1);
}
__global__ void __launch_bounds__(1024) k_scan() {
    __shared__ int sp[1024];
    int t = threadIdx.x;
    int c0 = g_cnt[4 * t], c1 = g_cnt[4 * t + 1], c2 = g_cnt[4 * t + 2], c3 = g_cnt[4 * t + 3];
    int s = c0 + c1 + c2 + c3;
    sp[t] = s;
    __syncthreads();
    for (int off = 1; off < 1024; off <<= 1) {
        int v = (t >= off) ? sp[t - off] : 0;
        __syncthreads();
        sp[t] += v;
        __syncthreads();
    }
    int base = sp[t] - s;
    g_off[4 * t] = base;
    g_off[4 * t + 1] = base + c0;
    g_off[4 * t + 2] = base + c0 + c1;
    g_off[4 * t + 3] = base + c0 + c1 + c2;
    if (t == 1023) g_off[NN] = sp[t];
}
__global__ void k_scatter(const int* __restrict__ ei, const int* __restrict__ et) {
    int e = blockIdx.x * 256 + threadIdx.x;
    int src = ei[e];
    int pos = g_off[src] + atomicAdd(&g_cur[src], 1);
    g_epack[pos] = ei[EE + e] | (et[e] << 12);
}
#define SCAP 80
__global__ void __launch_bounds__(128) k_sort() {
    __shared__ int buf[128][SCAP];
    int r = blockIdx.x * 128 + threadIdx.x;
    int s = g_off[r], e = g_off[r + 1];
    int n = e - s;
    if (n <= 1) return;
    if (n <= SCAP) {
        int* b = buf[threadIdx.x];
        for (int i = 0; i < n; i++) b[i] = g_epack[s + i];
        for (int i = 1; i < n; i++) {
            int key = b[i], kd = key & 0xFFF;
            int j = i - 1;
            while (j >= 0 && (b[j] & 0xFFF) > kd) { b[j + 1] = b[j]; j--; }
            b[j + 1] = key;
        }
        for (int i = 0; i < n; i++) g_epack[s + i] = b[i];
    } else {
        for (int i = s + 1; i < e; i++) {
            int key = g_epack[i], kd = key & 0xFFF;
            int j = i - 1;
            while (j >= s && (g_epack[j] & 0xFFF) > kd) { g_epack[j + 1] = g_epack[j]; j--; }
            g_epack[j + 1] = key;
        }
    }
}

// ---------------- 5. dense attention via mma.sync, double-buffered cp.async ----------------
__global__ void __launch_bounds__(256, 2) k_flash3() {
    extern __shared__ char sm[];
    const uint32_t sb = s2u(sm);
    const int tid = threadIdx.x, w = tid >> 5, lane = tid & 31;
    const int h = blockIdx.y, m0 = blockIdx.x * 128;
    const int g = lane >> 2, c = lane & 3;

    {
        const uint4* qsrc = ((const uint4*)g_qs) + (size_t)(h * NN + m0) * 8;
        for (int t2 = tid; t2 < 1024; t2 += 256) {
            int r = t2 >> 3, u = t2 & 7;
            *(uint4*)(sm + OQ + r * 144 + u * 16) = qsrc[r * 8 + u];
        }
        const char* ksrc = (const char*)(g_ks + (size_t)(h * NN) * 64);
        for (int t2 = tid; t2 < 1024; t2 += 256) {
            int r = t2 >> 3, u = t2 & 7;
            CPA16(sb + OKB + r * 144 + u * 16, ksrc + (size_t)(r * 8 + u) * 16);
        }
        for (int t2 = tid; t2 < 512; t2 += 256) {
            int d = t2 >> 4, u = t2 & 15;
            size_t go = ((size_t)(h * 32 + d) * NN) * 2 + u * 16;
            CPA16(sb + OVB + d * 272 + u * 16, (const char*)g_vth + go);
            CPA16(sb + OVB + 8704 + d * 272 + u * 16, (const char*)g_vtl + go);
        }
        CPA_COMMIT();
        CPA_WAIT0();
    }
    __syncthreads();

    uint32_t qf[4][4];
    {
        int r = (lane & 7) + ((lane >> 3) & 1) * 8;
        uint32_t base = sb + OQ + (w * 16 + r) * 144 + (lane >> 4) * 16;
        #pragma unroll
        for (int s = 0; s < 4; s++) LDM_X4(qf[s], base + s * 32);
    }

    float oacc[4][4];
    #pragma unroll
    for (int d = 0; d < 4; d++)
        #pragma unroll
        for (int i = 0; i < 4; i++) oacc[d][i] = 0.0f;
    float l0 = 0.0f, l1 = 0.0f;

    for (int t = 0; t < 32; t++) {
        __syncthreads();
        if (t + 1 < 32) {
            int jj = (t + 1) * 128, bi = (t + 1) & 1;
            const char* ksrc = (const char*)(g_ks + (size_t)(h * NN + jj) * 64);
            for (int t2 = tid; t2 < 1024; t2 += 256) {
                int r = t2 >> 3, u = t2 & 7;
                CPA16(sb + OKB + bi * 18432 + r * 144 + u * 16, ksrc + (size_t)(r * 8 + u) * 16);
            }
            for (int t2 = tid; t2 < 512; t2 += 256) {
                int d = t2 >> 4, u = t2 & 15;
                size_t go = ((size_t)(h * 32 + d) * NN + jj) * 2 + u * 16;
                CPA16(sb + OVB + bi * 17408 + d * 272 + u * 16, (const char*)g_vth + go);
                CPA16(sb + OVB + bi * 17408 + 8704 + d * 272 + u * 16, (const char*)g_vtl + go);
            }
            CPA_COMMIT();
            CPA_WAIT1();
        } else {
            CPA_WAIT0();
        }
        __syncthreads();

        const int bi = t & 1;
        const uint32_t kbase = sb + OKB + bi * 18432 + (lane & 7) * 144 + ((lane >> 3) & 1) * 16;
        const uint32_t vbh = sb + OVB + bi * 17408 + (lane & 7) * 272 + ((lane >> 3) & 1) * 16;
        const uint32_t vbl = vbh + 8704;

        #pragma unroll 1
        for (int kg = 0; kg < 8; kg++) {
            float sa2[4] = {0.f, 0.f, 0.f, 0.f};
            float sbv[4] = {0.f, 0.f, 0.f, 0.f};
            uint32_t b0[2], b1[2];
            uint32_t ka0 = kbase + (2 * kg) * (8 * 144);
            uint32_t ka1 = kbase + (2 * kg + 1) * (8 * 144);
            LDM_X2(b0, ka0);        LDM_X2(b1, ka0 + 32);
            MMA_BF16(sa2, qf[0], b0); MMA_BF16(sa2, qf[1], b1);
            MMA_BF16(sa2, qf[2], b0); MMA_BF16(sa2, qf[3], b1);
            LDM_X2(b0, ka0 + 64);   LDM_X2(b1, ka0 + 96);
            MMA_BF16(sa2, qf[0], b0); MMA_BF16(sa2, qf[1], b1);
            LDM_X2(b0, ka1);        LDM_X2(b1, ka1 + 32);
            MMA_BF16(sbv, qf[0], b0); MMA_BF16(sbv, qf[1], b1);
            MMA_BF16(sbv, qf[2], b0); MMA_BF16(sbv, qf[3], b1);
            LDM_X2(b0, ka1 + 64);   LDM_X2(b1, ka1 + 96);
            MMA_BF16(sbv, qf[0], b0); MMA_BF16(sbv, qf[1], b1);

            #pragma unroll
            for (int i = 0; i < 4; i++) { sa2[i] = mexp(sa2[i]); sbv[i] = mexp(sbv[i]); }
            l0 += sa2[0] + sa2[1] + sbv[0] + sbv[1];
            l1 += sa2[2] + sa2[3] + sbv[2] + sbv[3];

            uint32_t ah[4];
            CVT2(ah[0], sa2[1], sa2[0]);
            CVT2(ah[1], sa2[3], sa2[2]);
            CVT2(ah[2], sbv[1], sbv[0]);
            CVT2(ah[3], sbv[3], sbv[2]);

            #pragma unroll
            for (int d = 0; d < 4; d++) {
                uint32_t vh[2], vl[2];
                LDM_X2(vh, vbh + d * (8 * 272) + kg * 32);
                LDM_X2(vl, vbl + d * (8 * 272) + kg * 32);
                MMA_BF16(oacc[d], ah, vh);
                MMA_BF16(oacc[d], ah, vl);
            }
        }
    }

    l0 += __shfl_xor_sync(0xffffffffu, l0, 1);
    l0 += __shfl_xor_sync(0xffffffffu, l0, 2);
    l1 += __shfl_xor_sync(0xffffffffu, l1, 1);
    l1 += __shfl_xor_sync(0xffffffffu, l1, 2);
    int row0 = m0 + w * 16 + g;
    if (c == 0) {
        g_l[h * NN + row0] = l0;
        g_l[h * NN + row0 + 8] = l1;
    }
    float* o0 = g_att + (size_t)row0 * DD + h * 32;
    float* o1 = g_att + (size_t)(row0 + 8) * DD + h * 32;
    #pragma unroll
    for (int d = 0; d < 4; d++) {
        *(float2*)(o0 + d * 8 + 2 * c) = make_float2(oacc[d][0], oacc[d][1]);
        *(float2*)(o1 + d * 8 + 2 * c) = make_float2(oacc[d][2], oacc[d][3]);
    }
}

// ---------------- 6. sparse edge-bias correction ----------------
__global__ void __launch_bounds__(256) k_corr(const float* __restrict__ emb) {
    int t = blockIdx.x * 256 + threadIdx.x;
    int row = t >> 3, h = t & 7;
    int e = g_off[row], end = g_off[row + 1];
    if (e >= end) return;

    const float* qp = g_q + ((size_t)h * NN + row) * 32;
    float4 qv[8];
    #pragma unroll
    for (int i = 0; i < 8; i++) qv[i] = ((const float4*)qp)[i];
    const float* kh_ = g_k + (size_t)h * NN * 32;
    const float* vh_ = g_v + (size_t)h * NN * 32;

    float4 oa[8];
    #pragma unroll
    for (int i = 0; i < 8; i++) oa[i] = make_float4(0.f, 0.f, 0.f, 0.f);
    float lacc = 0.0f;
    const float scale = 0.17677669529663687f;

    while (e < end) {
        int pk = g_epack[e];
        int d = pk & 0xFFF;
        float bs = emb[(pk >> 12) * HH + h];
        e++;
        while (e < end && (g_epack[e] & 0xFFF) == d) {
            bs += emb[(g_epack[e] >> 12) * HH + h];
            e++;
        }
        const float4* kp = (const float4*)(kh_ + (size_t)d * 32);
        float s = 0.0f;
        #pragma unroll
        for (int i = 0; i < 8; i++) {
            float4 kk = kp[i];
            s += qv[i].x * kk.x + qv[i].y * kk.y + qv[i].z * kk.z + qv[i].w * kk.w;
        }
        float wgt = __expf(s * scale) * (__expf(bs) - 1.0f);
        lacc += wgt;
        const float4* vp = (const float4*)(vh_ + (size_t)d * 32);
        #pragma unroll
        for (int i = 0; i < 8; i++) {
            float4 vv = vp[i];
            oa[i].x += wgt * vv.x; oa[i].y += wgt * vv.y;
            oa[i].z += wgt * vv.z; oa[i].w += wgt * vv.w;
        }
    }

    g_l[h * NN + row] += lacc;
    float* dst = g_att + (size_t)row * DD + h * 32;
    #pragma unroll
    for (int i = 0; i < 8; i++) {
        float4 cur = ((float4*)dst)[i];
        ((float4*)dst)[i] = make_float4(cur.x + oa[i].x, cur.y + oa[i].y,
                                        cur.z + oa[i].z, cur.w + oa[i].w);
    }
}

// ---------------- 7. normalize att + split to bf16 hi/lo ----------------
__global__ void k_split_att() {
    int idx = blockIdx.x * 256 + threadIdx.x;     // float4 over N*D
    int n = idx >> 6, c = (idx & 63) * 4;
    int h = c >> 5;
    float inv = 1.0f / g_l[h * NN + n];
    float4 a = ((const float4*)g_att)[idx];
    float v[4] = {a.x * inv, a.y * inv, a.z * inv, a.w * inv};
    __nv_bfloat16 hi[4], lo[4];
    #pragma unroll
    for (int j = 0; j < 4; j++) {
        hi[j] = __float2bfloat16(v[j]);
        lo[j] = __float2bfloat16(v[j] - __bfloat162float(hi[j]));
    }
    *(uint2*)(g_as + (size_t)n * 512 + c) = *(uint2*)hi;
    *(uint2*)(g_as + (size_t)n * 512 + 256 + c) = *(uint2*)lo;
}

// ---------------- 8. O-projection via mma.sync: tmp = x + attn@Wo + bo ----------------
__global__ void __launch_bounds__(256, 2) k_oprojmma(const float* __restrict__ bo,
                                                     const float* __restrict__ x) {
    __shared__ __align__(16) char As[128 * 144];
    __shared__ __align__(16) char Bs[128 * 144];
    const uint32_t sa = s2u(As), sbm = s2u(Bs);
    const int tid = threadIdx.x, w = tid >> 5, lane = tid & 31;
    const int g = lane >> 2, c = lane & 3;
    const int m0 = blockIdx.y * 128, cb = blockIdx.x * 128;
    const int mr = (w & 3) * 32, nc = (w >> 2) * 64;
    const __nv_bfloat16* wt = g_wt + ((size_t)(3 * 256 + cb)) * 512;

    float acc[2][8][4];
    #pragma unroll
    for (int mi = 0; mi < 2; mi++)
        #pragma unroll
        for (int nt = 0; nt < 8; nt++)
            #pragma unroll
            for (int i = 0; i < 4; i++) acc[mi][nt][i] = 0.0f;

    for (int ks = 0; ks < 8; ks++) {
        int kk = ks * 32;
        __syncthreads();
        #pragma unroll
        for (int i = tid; i < 1024; i += 256) {
            int r = i >> 3, u = i & 7;
            int go = (u < 4) ? (kk + u * 8) : (256 + kk + (u - 4) * 8);
            *(uint4*)(As + r * 144 + u * 16) =
                *(const uint4*)(g_as + (size_t)(m0 + r) * 512 + go);
            *(uint4*)(Bs + r * 144 + u * 16) =
                *(const uint4*)(wt + (size_t)r * 512 + go);
        }
        __syncthreads();
        #pragma unroll
        for (int kh = 0; kh < 2; kh++) {
            uint32_t ah[2][4], al[2][4];
            int rr = (lane & 7) + ((lane >> 3) & 1) * 8;
            #pragma unroll
            for (int mi = 0; mi < 2; mi++) {
                uint32_t base = sa + (mr + mi * 16 + rr) * 144 + kh * 32 + (lane >> 4) * 16;
                LDM_X4(ah[mi], base);
                LDM_X4(al[mi], base + 64);
            }
            #pragma unroll
            for (int nt = 0; nt < 8; nt++) {
                uint32_t bh[2], bl[2];
                uint32_t bb = sbm + (nc + nt * 8 + (lane & 7)) * 144 + kh * 32 +
                              ((lane >> 3) & 1) * 16;
                LDM_X2(bh, bb);
                LDM_X2(bl, bb + 64);
                #pragma unroll
                for (int mi = 0; mi < 2; mi++) {
                    MMA_BF16(acc[mi][nt], ah[mi], bh);
                    MMA_BF16(acc[mi][nt], ah[mi], bl);
                    MMA_BF16(acc[mi][nt], al[mi], bh);
                }
            }
        }
    }

    #pragma unroll
    for (int mi = 0; mi < 2; mi++) {
        int row0 = m0 + mr + mi * 16 + g;
        #pragma unroll
        for (int nt = 0; nt < 8; nt++) {
            int c0 = cb + nc + nt * 8 + 2 * c;
            float b0 = bo[c0], b1 = bo[c0 + 1];
            float2 x0 = *(const float2*)(x + (size_t)row0 * DD + c0);
            float2 x1 = *(const float2*)(x + (size_t)(row0 + 8) * DD + c0);
            *(float2*)(g_tmp + (size_t)row0 * DD + c0) =
                make_float2(acc[mi][nt][0] + b0 + x0.x, acc[mi][nt][1] + b1 + x0.y);
            *(float2*)(g_tmp + (size_t)(row0 + 8) * DD + c0) =
                make_float2(acc[mi][nt][2] + b0 + x1.x, acc[mi][nt][3] + b1 + x1.y);
        }
    }
}

// ---------------- 9. LayerNorm ----------------
__global__ void __launch_bounds__(256) k_ln(const float* __restrict__ gamma,
                                            const float* __restrict__ beta,
                                            float* __restrict__ out) {
    const int n = blockIdx.x, tid = threadIdx.x;
    float v = g_tmp[(size_t)n * DD + tid];
    __shared__ float red[8];
    float s = v;
    #pragma unroll
    for (int o = 16; o > 0; o >>= 1) s += __shfl_xor_sync(0xffffffffu, s, o);
    if ((tid & 31) == 0) red[tid >> 5] = s;
    __syncthreads();
    float tot = 0.f;
    #pragma unroll
    for (int i = 0; i < 8; i++) tot += red[i];
    float mu = tot * (1.0f / DD);
    float d = v - mu;
    __syncthreads();
    float sq = d * d;
    #pragma unroll
    for (int o = 16; o > 0; o >>= 1) sq += __shfl_xor_sync(0xffffffffu, sq, o);
    if ((tid & 31) == 0) red[tid >> 5] = sq;
    __syncthreads();
    float tot2 = 0.f;
    #pragma unroll
    for (int i = 0; i < 8; i++) tot2 += red[i];
    float var = tot2 * (1.0f / DD);
    out[(size_t)n * DD + tid] = d * rsqrtf(var + 1e-5f) * gamma[tid] + beta[tid];
}

// ---------------- launch ----------------
extern "C" void kernel_launch(void* const* d_in, const int* in_sizes, int n_in,
                              void* d_out, int out_size) {
    const float* x       = (const float*)d_in[0];
    const float* pos     = (const float*)d_in[1];
    const int* ei        = (const int*)d_in[2];
    const int* et        = (const int*)d_in[3];
    const float* Wq = (const float*)d_in[4];
    const float* bq = (const float*)d_in[5];
    const float* Wk = (const float*)d_in[6];
    const float* bk = (const float*)d_in[7];
    const float* Wv = (const float*)d_in[8];
    const float* bv = (const float*)d_in[9];
    const float* Wo = (const float*)d_in[10];
    const float* bo = (const float*)d_in[11];
    const float* emb   = (const float*)d_in[12];
    const float* gamma = (const float*)d_in[13];
    const float* beta  = (const float*)d_in[14];
    float* out = (float*)d_out;

    cudaFuncSetAttribute(k_flash3, cudaFuncAttributeMaxDynamicSharedMemorySize, SM3);

    k_preph<<<(NN * DD / 4) / 256, 256>>>(x, pos);
    k_prepw<<<128, 256>>>(Wq, Wk, Wv, Wo);
    k_qkvmma<<<dim3(6, NN / 128), 256>>>(bq, bk, bv);
    k_split_vt<<<HH * NN / 256, 256>>>();
    k_zero<<<(NN + 255) / 256, 256>>>();
    k_count<<<EE / 256, 256>>>(ei);
    k_scan<<<1, 1024>>>();
    k_scatter<<<EE / 256, 256>>>(ei, et);
    k_sort<<<NN / 128, 128>>>();
    k_flash3<<<dim3(NN / 128, HH), 256, SM3>>>();
    k_corr<<<(NN * HH) / 256, 256>>>(emb);
    k_split_att<<<(NN * DD / 4) / 256, 256>>>();
    k_oprojmma<<<dim3(2, NN / 128), 256>>>(bo, x);
    k_ln<<<NN, 256>>>(gamma, beta, out);
}

// round 14
// speedup vs baseline: 1.3715x; 1.3715x over previous
#include <cuda_runtime.h>
#include <cuda_bf16.h>
#include <cstdint>

#define NN 4096
#define DD 256
#define HH 8
#define DHH 32
#define EE 131072

// ---------------- scratch ----------------
__device__ float g_q[HH * NN * DHH];
__device__ float g_k[HH * NN * DHH];
__device__ float g_v[HH * NN * DHH];
__device__ float g_att[NN * DD];      // unnormalized attn out
__device__ float g_l[HH * NN];        // row sums
__device__ float g_tmp[NN * DD];
// CSR of edges keyed by source row (sorted by dst within row)
__device__ int g_cnt[NN];
__device__ int g_cur[NN];
__device__ int g_off[NN + 1];
__device__ int g_epack[EE];           // dst | (type<<12)
// split-bf16 operands
__device__ __nv_bfloat16 g_qs[HH * NN * 64];   // per row: [hi 32][lo 32], q pre-scaled
__device__ __nv_bfloat16 g_ks[HH * NN * 64];
__device__ __nv_bfloat16 g_vth[HH * 32 * NN];  // V^T hi  [h][d][n]
__device__ __nv_bfloat16 g_vtl[HH * 32 * NN];  // V^T lo
__device__ __nv_bfloat16 g_vs[HH * NN * 32];   // V hi, row-major [h][n][dh] (for k_corr)

// ---------------- flash3 smem layout (dynamic, double-buffered K/V) ----------------
#define OQ    0
#define OKB   18432                 // K bufs: +bi*18432  (128 x 144B)
#define OVB   55296                 // V bufs: +bi*17408; hi at +0, lo at +8704 (32 x 272B)
#define SM3   90112

// ---------------- packed fp32x2 helpers ----------------
#define PACK2(u, lo, hi) asm("mov.b64 %0, {%1,%2};" : "=l"(u) : "f"(lo), "f"(hi))
#define UNPACK2(lo, hi, u) asm("mov.b64 {%0,%1}, %2;" : "=f"(lo), "=f"(hi) : "l"(u))
#define FMA2(d, a, b) asm("fma.rn.f32x2 %0, %1, %2, %0;" : "+l"(d) : "l"(a), "l"(b))

__device__ __forceinline__ uint32_t s2u(const void* p) {
    uint32_t a;
    asm("{ .reg .u64 t; cvta.to.shared.u64 t, %1; cvt.u32.u64 %0, t; }" : "=r"(a) : "l"(p));
    return a;
}

// exp via MUFU pipe (overlaps with FMA + tensor pipes)
__device__ __forceinline__ float mexp(float s) {
    float r;
    asm("ex2.approx.f32 %0, %1;" : "=f"(r) : "f"(s * 1.4426950408889634f));
    return r;
}

#define LDM_X2(r_, a_)                                                         \
    asm volatile("ldmatrix.sync.aligned.m8n8.x2.shared.b16 {%0,%1}, [%2];"     \
                 : "=r"((r_)[0]), "=r"((r_)[1]) : "r"(a_))
#define LDM_X4(r_, a_)                                                         \
    asm volatile("ldmatrix.sync.aligned.m8n8.x4.shared.b16 {%0,%1,%2,%3}, [%4];" \
                 : "=r"((r_)[0]), "=r"((r_)[1]), "=r"((r_)[2]), "=r"((r_)[3]) : "r"(a_))
#define MMA_BF16(c_, a_, b_)                                                   \
    asm volatile("mma.sync.aligned.m16n8k16.row.col.f32.bf16.bf16.f32 "        \
                 "{%0,%1,%2,%3}, {%4,%5,%6,%7}, {%8,%9}, {%0,%1,%2,%3};"       \
                 : "+f"((c_)[0]), "+f"((c_)[1]), "+f"((c_)[2]), "+f"((c_)[3])  \
                 : "r"((a_)[0]), "r"((a_)[1]), "r"((a_)[2]), "r"((a_)[3]),     \
                   "r"((b_)[0]), "r"((b_)[1]))
#define CPA16(dst, src) \
    asm volatile("cp.async.ca.shared.global [%0], [%1], 16;" :: "r"(dst), "l"(src))
#define CPA_COMMIT() asm volatile("cp.async.commit_group;" ::: "memory")
#define CPA_WAIT0() asm volatile("cp.async.wait_group 0;" ::: "memory")
#define CPA_WAIT1() asm volatile("cp.async.wait_group 1;" ::: "memory")

// ---------------- 1. QKV projections (x+pos fused in, split-bf16 fused out) ----------------
__global__ void __launch_bounds__(256) k_qkv(
    const float* __restrict__ x, const float* __restrict__ pos,
    const float* __restrict__ Wq, const float* __restrict__ bq,
    const float* __restrict__ Wk, const float* __restrict__ bk,
    const float* __restrict__ Wv, const float* __restrict__ bv) {
    const int z = blockIdx.z;
    const float* W;
    const float* bias;
    float* out;
    if (z == 0)      { W = Wq; bias = bq; out = g_q; }
    else if (z == 1) { W = Wk; bias = bk; out = g_k; }
    else             { W = Wv; bias = bv; out = g_v; }

    __shared__ __align__(16) float AsT[32][68];   // [k][row]
    __shared__ __align__(16) float Bs2[32][68];   // [k][col]
    const int m0 = blockIdx.y * 64, n0 = blockIdx.x * 64;
    const int tid = threadIdx.x, tx = tid & 15, ty = tid >> 4;

    unsigned long long acc[4][2];
    #pragma unroll
    for (int i = 0; i < 4; i++) { acc[i][0] = 0ull; acc[i][1] = 0ull; }

    for (int kk = 0; kk < DD; kk += 32) {
        #pragma unroll
        for (int i = tid; i < 64 * 32; i += 256) {
            int r = i >> 5, c = i & 31;
            int gi = (m0 + r) * DD + kk + c;
            AsT[c][r] = x[gi] + pos[gi];
        }
        #pragma unroll
        for (int i = tid; i < 32 * 64; i += 256) {
            int r = i >> 6, c = i & 63;
            Bs2[r][c] = W[(kk + r) * DD + n0 + c];
        }
        __syncthreads();
        #pragma unroll 8
        for (int kq = 0; kq < 32; kq++) {
            float4 a = *(const float4*)&AsT[kq][ty * 4];
            ulonglong2 b = *(const ulonglong2*)&Bs2[kq][tx * 4];
            float av[4] = {a.x, a.y, a.z, a.w};
            #pragma unroll
            for (int r = 0; r < 4; r++) {
                unsigned long long ap;
                PACK2(ap, av[r], av[r]);
                FMA2(acc[r][0], ap, b.x);
                FMA2(acc[r][1], ap, b.y);
            }
        }
        __syncthreads();
    }

    __nv_bfloat16* sp = (z == 0) ? g_qs : g_ks;
    const float sc = (z == 0) ? 0.17677669529663687f : 1.0f;
    #pragma unroll
    for (int i = 0; i < 4; i++) {
        int row = m0 + ty * 4 + i;
        float v0, v1, v2, v3;
        UNPACK2(v0, v1, acc[i][0]);
        UNPACK2(v2, v3, acc[i][1]);
        float vv[4] = {v0, v1, v2, v3};
        int col0 = n0 + tx * 4;
        int hh2 = col0 >> 5, dh0 = col0 & 31;
        if (z < 2) {
            #pragma unroll
            for (int j = 0; j < 4; j++) {
                int col = col0 + j;
                float val = vv[j] + bias[col];
                out[((size_t)hh2 * NN + row) * DHH + (col & 31)] = val;
                float sv = val * sc;
                __nv_bfloat16 hi = __float2bfloat16(sv);
                size_t base = ((size_t)hh2 * NN + row) * 64 + (col & 31);
                sp[base] = hi;
                sp[base + 32] = __float2bfloat16(sv - __bfloat162float(hi));
            }
        } else {
            __nv_bfloat16 hv[4];
            #pragma unroll
            for (int j = 0; j < 4; j++) {
                int col = col0 + j;
                float val = vv[j] + bias[col];
                out[((size_t)hh2 * NN + row) * DHH + (col & 31)] = val;
                hv[j] = __float2bfloat16(val);
            }
            // row-major bf16 V (hi) for k_corr; dh0 is 4-aligned -> 8B aligned store
            *(uint2*)(g_vs + ((size_t)hh2 * NN + row) * 32 + dh0) = *(uint2*)hv;
        }
    }
}

// ---------------- 2. V^T hi/lo split ----------------
__global__ void k_split_vt() {
    int idx = blockIdx.x * 256 + threadIdx.x;     // h*NN+n
    int hh2 = idx >> 12, n = idx & 4095;
    const float* src = g_v + (size_t)idx * 32;
    #pragma unroll
    for (int d = 0; d < 32; d++) {
        float v = src[d];
        __nv_bfloat16 hi = __float2bfloat16(v);
        size_t o = (size_t)(hh2 * 32 + d) * NN + n;
        g_vth[o] = hi;
        g_vtl[o] = __float2bfloat16(v - __bfloat162float(hi));
    }
}

// ---------------- 3. CSR build + per-row dst sort ----------------
__global__ void k_zero() {
    int i = blockIdx.x * 256 + threadIdx.x;
    if (i < NN) { g_cnt[i] = 0; g_cur[i] = 0; }
}
__global__ void k_count(const int* __restrict__ ei) {
    int e = blockIdx.x * 256 + threadIdx.x;
    atomicAdd(&g_cnt[ei[e]], 1);
}
__global__ void __launch_bounds__(1024) k_scan() {
    __shared__ int sp[1024];
    int t = threadIdx.x;
    int c0 = g_cnt[4 * t], c1 = g_cnt[4 * t + 1], c2 = g_cnt[4 * t + 2], c3 = g_cnt[4 * t + 3];
    int s = c0 + c1 + c2 + c3;
    sp[t] = s;
    __syncthreads();
    for (int off = 1; off < 1024; off <<= 1) {
        int v = (t >= off) ? sp[t - off] : 0;
        __syncthreads();
        sp[t] += v;
        __syncthreads();
    }
    int base = sp[t] - s;
    g_off[4 * t] = base;
    g_off[4 * t + 1] = base + c0;
    g_off[4 * t + 2] = base + c0 + c1;
    g_off[4 * t + 3] = base + c0 + c1 + c2;
    if (t == 1023) g_off[NN] = sp[t];
}
__global__ void k_scatter(const int* __restrict__ ei, const int* __restrict__ et) {
    int e = blockIdx.x * 256 + threadIdx.x;
    int src = ei[e];
    int pos = g_off[src] + atomicAdd(&g_cur[src], 1);
    g_epack[pos] = ei[EE + e] | (et[e] << 12);
}
#define SCAP 80
__global__ void __launch_bounds__(128) k_sort() {
    __shared__ int buf[128][SCAP];
    int r = blockIdx.x * 128 + threadIdx.x;
    int s = g_off[r], e = g_off[r + 1];
    int n = e - s;
    if (n <= 1) return;
    if (n <= SCAP) {
        int* b = buf[threadIdx.x];
        for (int i = 0; i < n; i++) b[i] = g_epack[s + i];
        for (int i = 1; i < n; i++) {
            int key = b[i], kd = key & 0xFFF;
            int j = i - 1;
            while (j >= 0 && (b[j] & 0xFFF) > kd) { b[j + 1] = b[j]; j--; }
            b[j + 1] = key;
        }
        for (int i = 0; i < n; i++) g_epack[s + i] = b[i];
    } else {
        for (int i = s + 1; i < e; i++) {
            int key = g_epack[i], kd = key & 0xFFF;
            int j = i - 1;
            while (j >= s && (g_epack[j] & 0xFFF) > kd) { g_epack[j + 1] = g_epack[j]; j--; }
            g_epack[j + 1] = key;
        }
    }
}

// ---------------- 4. dense attention via mma.sync, double-buffered cp.async ----------------
// grid (NN/128, HH), 256 threads (8 warps x 16 rows). O and l written unnormalized.
__global__ void __launch_bounds__(256, 2) k_flash3() {
    extern __shared__ char sm[];
    const uint32_t sb = s2u(sm);
    const int tid = threadIdx.x, w = tid >> 5, lane = tid & 31;
    const int h = blockIdx.y, m0 = blockIdx.x * 128;
    const int g = lane >> 2, c = lane & 3;

    // prologue: Q tile (plain stores) + tile 0 K/V via cp.async group 0
    {
        const uint4* qsrc = ((const uint4*)g_qs) + (size_t)(h * NN + m0) * 8;
        for (int t2 = tid; t2 < 1024; t2 += 256) {
            int r = t2 >> 3, u = t2 & 7;
            *(uint4*)(sm + OQ + r * 144 + u * 16) = qsrc[r * 8 + u];
        }
        const char* ksrc = (const char*)(g_ks + (size_t)(h * NN) * 64);
        for (int t2 = tid; t2 < 1024; t2 += 256) {
            int r = t2 >> 3, u = t2 & 7;
            CPA16(sb + OKB + r * 144 + u * 16, ksrc + (size_t)(r * 8 + u) * 16);
        }
        for (int t2 = tid; t2 < 512; t2 += 256) {
            int d = t2 >> 4, u = t2 & 15;
            size_t go = ((size_t)(h * 32 + d) * NN) * 2 + u * 16;
            CPA16(sb + OVB + d * 272 + u * 16, (const char*)g_vth + go);
            CPA16(sb + OVB + 8704 + d * 272 + u * 16, (const char*)g_vtl + go);
        }
        CPA_COMMIT();
        CPA_WAIT0();
    }
    __syncthreads();

    // persistent Q A-fragments: [Qh u0][Qh u1][Ql u0][Ql u1]
    uint32_t qf[4][4];
    {
        int r = (lane & 7) + ((lane >> 3) & 1) * 8;
        uint32_t base = sb + OQ + (w * 16 + r) * 144 + (lane >> 4) * 16;
        #pragma unroll
        for (int s = 0; s < 4; s++) LDM_X4(qf[s], base + s * 32);
    }

    float oacc[4][4];
    #pragma unroll
    for (int d = 0; d < 4; d++)
        #pragma unroll
        for (int i = 0; i < 4; i++) oacc[d][i] = 0.0f;
    float l0 = 0.0f, l1 = 0.0f;

    for (int t = 0; t < 32; t++) {
        __syncthreads();
        if (t + 1 < 32) {
            int jj = (t + 1) * 128, bi = (t + 1) & 1;
            const char* ksrc = (const char*)(g_ks + (size_t)(h * NN + jj) * 64);
            for (int t2 = tid; t2 < 1024; t2 += 256) {
                int r = t2 >> 3, u = t2 & 7;
                CPA16(sb + OKB + bi * 18432 + r * 144 + u * 16, ksrc + (size_t)(r * 8 + u) * 16);
            }
            for (int t2 = tid; t2 < 512; t2 += 256) {
                int d = t2 >> 4, u = t2 & 15;
                size_t go = ((size_t)(h * 32 + d) * NN + jj) * 2 + u * 16;
                CPA16(sb + OVB + bi * 17408 + d * 272 + u * 16, (const char*)g_vth + go);
                CPA16(sb + OVB + bi * 17408 + 8704 + d * 272 + u * 16, (const char*)g_vtl + go);
            }
            CPA_COMMIT();
            CPA_WAIT1();
        } else {
            CPA_WAIT0();
        }
        __syncthreads();

        const int bi = t & 1;
        const uint32_t kbase = sb + OKB + bi * 18432 + (lane & 7) * 144 + ((lane >> 3) & 1) * 16;
        const uint32_t vbh = sb + OVB + bi * 17408 + (lane & 7) * 272 + ((lane >> 3) & 1) * 16;
        const uint32_t vbl = vbh + 8704;

        #pragma unroll 1
        for (int kg = 0; kg < 8; kg++) {
            float sa[4] = {0.f, 0.f, 0.f, 0.f};
            float sbv[4] = {0.f, 0.f, 0.f, 0.f};
            uint32_t b0[2], b1[2];
            uint32_t ka0 = kbase + (2 * kg) * (8 * 144);
            uint32_t ka1 = kbase + (2 * kg + 1) * (8 * 144);
            LDM_X2(b0, ka0);        LDM_X2(b1, ka0 + 32);
            MMA_BF16(sa, qf[0], b0); MMA_BF16(sa, qf[1], b1);
            MMA_BF16(sa, qf[2], b0); MMA_BF16(sa, qf[3], b1);
            LDM_X2(b0, ka0 + 64);   LDM_X2(b1, ka0 + 96);
            MMA_BF16(sa, qf[0], b0); MMA_BF16(sa, qf[1], b1);
            LDM_X2(b0, ka1);        LDM_X2(b1, ka1 + 32);
            MMA_BF16(sbv, qf[0], b0); MMA_BF16(sbv, qf[1], b1);
            MMA_BF16(sbv, qf[2], b0); MMA_BF16(sbv, qf[3], b1);
            LDM_X2(b0, ka1 + 64);   LDM_X2(b1, ka1 + 96);
            MMA_BF16(sbv, qf[0], b0); MMA_BF16(sbv, qf[1], b1);

            // exp on the MUFU pipe (overlaps tensor + FMA work)
            #pragma unroll
            for (int i = 0; i < 4; i++) { sa[i] = mexp(sa[i]); sbv[i] = mexp(sbv[i]); }
            l0 += sa[0] + sa[1] + sbv[0] + sbv[1];
            l1 += sa[2] + sa[3] + sbv[2] + sbv[3];

            // P in bf16 (hi only)
            uint32_t ah[4];
            asm("cvt.rn.bf16x2.f32 %0, %1, %2;" : "=r"(ah[0]) : "f"(sa[1]), "f"(sa[0]));
            asm("cvt.rn.bf16x2.f32 %0, %1, %2;" : "=r"(ah[1]) : "f"(sa[3]), "f"(sa[2]));
            asm("cvt.rn.bf16x2.f32 %0, %1, %2;" : "=r"(ah[2]) : "f"(sbv[1]), "f"(sbv[0]));
            asm("cvt.rn.bf16x2.f32 %0, %1, %2;" : "=r"(ah[3]) : "f"(sbv[3]), "f"(sbv[2]));

            #pragma unroll
            for (int d = 0; d < 4; d++) {
                uint32_t vh[2], vl[2];
                LDM_X2(vh, vbh + d * (8 * 272) + kg * 32);
                LDM_X2(vl, vbl + d * (8 * 272) + kg * 32);
                MMA_BF16(oacc[d], ah, vh);
                MMA_BF16(oacc[d], ah, vl);
            }
        }
    }

    l0 += __shfl_xor_sync(0xffffffffu, l0, 1);
    l0 += __shfl_xor_sync(0xffffffffu, l0, 2);
    l1 += __shfl_xor_sync(0xffffffffu, l1, 1);
    l1 += __shfl_xor_sync(0xffffffffu, l1, 2);
    int row0 = m0 + w * 16 + g;
    if (c == 0) {
        g_l[h * NN + row0] = l0;
        g_l[h * NN + row0 + 8] = l1;
    }
    float* o0 = g_att + (size_t)row0 * DD + h * 32;
    float* o1 = g_att + (size_t)(row0 + 8) * DD + h * 32;
    #pragma unroll
    for (int d = 0; d < 4; d++) {
        *(float2*)(o0 + d * 8 + 2 * c) = make_float2(oacc[d][0], oacc[d][1]);
        *(float2*)(o1 + d * 8 + 2 * c) = make_float2(oacc[d][2], oacc[d][3]);
    }
}

// ---------------- 5. sparse edge-bias correction (bf16 K/V: 4x less L2 traffic) ----------------
__global__ void __launch_bounds__(256) k_corr(const float* __restrict__ emb) {
    int t = blockIdx.x * 256 + threadIdx.x;
    int row = t >> 3, h = t & 7;
    int e = g_off[row], end = g_off[row + 1];
    if (e >= end) return;

    const float* qp = g_q + ((size_t)h * NN + row) * 32;
    float4 qv[8];
    #pragma unroll
    for (int i = 0; i < 8; i++) qv[i] = ((const float4*)qp)[i];
    const __nv_bfloat16* kh_ = g_ks + (size_t)h * NN * 64;   // hi half at row*64
    const __nv_bfloat16* vh_ = g_vs + (size_t)h * NN * 32;

    float4 oa[8];
    #pragma unroll
    for (int i = 0; i < 8; i++) oa[i] = make_float4(0.f, 0.f, 0.f, 0.f);
    float lacc = 0.0f;
    const float scale = 0.17677669529663687f;

    while (e < end) {
        int pk = g_epack[e];
        int d = pk & 0xFFF;
        float bs = emb[(pk >> 12) * HH + h];
        e++;
        while (e < end && (g_epack[e] & 0xFFF) == d) {
            bs += emb[(g_epack[e] >> 12) * HH + h];
            e++;
        }
        // score from bf16-hi K (error ~2^-9 on a ~3% correction term: negligible)
        const __nv_bfloat162* kp = (const __nv_bfloat162*)(kh_ + (size_t)d * 64);
        float s = 0.0f;
        #pragma unroll
        for (int i = 0; i < 8; i++) {
            float2 a = __bfloat1622float2(kp[2 * i]);
            float2 b = __bfloat1622float2(kp[2 * i + 1]);
            s += qv[i].x * a.x + qv[i].y * a.y + qv[i].z * b.x + qv[i].w * b.y;
        }
        float wgt = __expf(s * scale) * (__expf(bs) - 1.0f);
        lacc += wgt;
        const __nv_bfloat162* vp = (const __nv_bfloat162*)(vh_ + (size_t)d * 32);
        #pragma unroll
        for (int i = 0; i < 8; i++) {
            float2 a = __bfloat1622float2(vp[2 * i]);
            float2 b = __bfloat1622float2(vp[2 * i + 1]);
            oa[i].x += wgt * a.x; oa[i].y += wgt * a.y;
            oa[i].z += wgt * b.x; oa[i].w += wgt * b.y;
        }
    }

    g_l[h * NN + row] += lacc;
    float* dst = g_att + (size_t)row * DD + h * 32;
    #pragma unroll
    for (int i = 0; i < 8; i++) {
        float4 cur = ((float4*)dst)[i];
        ((float4*)dst)[i] = make_float4(cur.x + oa[i].x, cur.y + oa[i].y,
                                        cur.z + oa[i].z, cur.w + oa[i].w);
    }
}

// ---------------- 6. tmp = x + (att/l) @ Wo + bo  (normalization fused) ----------------
__global__ void __launch_bounds__(256) k_oproj(const float* __restrict__ Wo,
                                               const float* __restrict__ bo,
                                               const float* __restrict__ x) {
    __shared__ __align__(16) float AsT[32][68];
    __shared__ __align__(16) float Bs2[32][68];
    __shared__ float invl[64][8];
    const int m0 = blockIdx.y * 64, n0 = blockIdx.x * 64;
    const int tid = threadIdx.x, tx = tid & 15, ty = tid >> 4;

    #pragma unroll
    for (int i = tid; i < 512; i += 256) {
        int r = i >> 3, hh2 = i & 7;
        invl[r][hh2] = 1.0f / g_l[hh2 * NN + m0 + r];
    }
    __syncthreads();

    unsigned long long acc[4][2];
    #pragma unroll
    for (int i = 0; i < 4; i++) { acc[i][0] = 0ull; acc[i][1] = 0ull; }

    for (int kk = 0; kk < DD; kk += 32) {
        #pragma unroll
        for (int i = tid; i < 64 * 32; i += 256) {
            int r = i >> 5, c = i & 31;
            AsT[c][r] = g_att[(m0 + r) * DD + kk + c] * invl[r][(kk + c) >> 5];
        }
        #pragma unroll
        for (int i = tid; i < 32 * 64; i += 256) {
            int r = i >> 6, c = i & 63;
            Bs2[r][c] = Wo[(kk + r) * DD + n0 + c];
        }
        __syncthreads();
        #pragma unroll 8
        for (int kq = 0; kq < 32; kq++) {
            float4 a = *(const float4*)&AsT[kq][ty * 4];
            ulonglong2 b = *(const ulonglong2*)&Bs2[kq][tx * 4];
            float av[4] = {a.x, a.y, a.z, a.w};
            #pragma unroll
            for (int r = 0; r < 4; r++) {
                unsigned long long ap;
                PACK2(ap, av[r], av[r]);
                FMA2(acc[r][0], ap, b.x);
                FMA2(acc[r][1], ap, b.y);
            }
        }
        __syncthreads();
    }
    #pragma unroll
    for (int i = 0; i < 4; i++) {
        int row = m0 + ty * 4 + i;
        float v0, v1, v2, v3;
        UNPACK2(v0, v1, acc[i][0]);
        UNPACK2(v2, v3, acc[i][1]);
        float vv[4] = {v0, v1, v2, v3};
        #pragma unroll
        for (int j = 0; j < 4; j++) {
            int col = n0 + tx * 4 + j;
            g_tmp[(size_t)row * DD + col] = vv[j] + bo[col] + x[(size_t)row * DD + col];
        }
    }
}

// ---------------- 7. LayerNorm ----------------
__global__ void __launch_bounds__(256) k_ln(const float* __restrict__ gamma,
                                            const float* __restrict__ beta,
                                            float* __restrict__ out) {
    const int n = blockIdx.x, tid = threadIdx.x;
    float v = g_tmp[(size_t)n * DD + tid];
    __shared__ float red[8];
    float s = v;
    #pragma unroll
    for (int o = 16; o > 0; o >>= 1) s += __shfl_xor_sync(0xffffffffu, s, o);
    if ((tid & 31) == 0) red[tid >> 5] = s;
    __syncthreads();
    float tot = 0.f;
    #pragma unroll
    for (int i = 0; i < 8; i++) tot += red[i];
    float mu = tot * (1.0f / DD);
    float d = v - mu;
    __syncthreads();
    float sq = d * d;
    #pragma unroll
    for (int o = 16; o > 0; o >>= 1) sq += __shfl_xor_sync(0xffffffffu, sq, o);
    if ((tid & 31) == 0) red[tid >> 5] = sq;
    __syncthreads();
    float tot2 = 0.f;
    #pragma unroll
    for (int i = 0; i < 8; i++) tot2 += red[i];
    float var = tot2 * (1.0f / DD);
    out[(size_t)n * DD + tid] = d * rsqrtf(var + 1e-5f) * gamma[tid] + beta[tid];
}

// ---------------- launch ----------------
extern "C" void kernel_launch(void* const* d_in, const int* in_sizes, int n_in,
                              void* d_out, int out_size) {
    const float* x       = (const float*)d_in[0];
    const float* pos     = (const float*)d_in[1];
    const int* ei        = (const int*)d_in[2];
    const int* et        = (const int*)d_in[3];
    const float* Wq = (const float*)d_in[4];
    const float* bq = (const float*)d_in[5];
    const float* Wk = (const float*)d_in[6];
    const float* bk = (const float*)d_in[7];
    const float* Wv = (const float*)d_in[8];
    const float* bv = (const float*)d_in[9];
    const float* Wo = (const float*)d_in[10];
    const float* bo = (const float*)d_in[11];
    const float* emb   = (const float*)d_in[12];
    const float* gamma = (const float*)d_in[13];
    const float* beta  = (const float*)d_in[14];
    float* out = (float*)d_out;

    cudaFuncSetAttribute(k_flash3, cudaFuncAttributeMaxDynamicSharedMemorySize, SM3);

    k_qkv<<<dim3(DD / 64, NN / 64, 3), 256>>>(x, pos, Wq, bq, Wk, bk, Wv, bv);
    k_split_vt<<<HH * NN / 256, 256>>>();
    k_zero<<<(NN + 255) / 256, 256>>>();
    k_count<<<EE / 256, 256>>>(ei);
    k_scan<<<1, 1024>>>();
    k_scatter<<<EE / 256, 256>>>(ei, et);
    k_sort<<<NN / 128, 128>>>();
    k_flash3<<<dim3(NN / 128, HH), 256, SM3>>>();
    k_corr<<<(NN * HH) / 256, 256>>>(emb);
    k_oproj<<<dim3(DD / 64, NN / 64), 256>>>(Wo, bo, x);
    k_ln<<<NN, 256>>>(gamma, beta, out);
}

// round 15
// speedup vs baseline: 1.6229x; 1.1833x over previous
#include <cuda_runtime.h>
#include <cuda_bf16.h>
#include <cstdint>

#define NN 4096
#define DD 256
#define HH 8
#define DHH 32
#define EE 131072
#define BCAP 96

// ---------------- scratch ----------------
__device__ float g_q[HH * NN * DHH];
__device__ float g_k[HH * NN * DHH];
__device__ float g_v[HH * NN * DHH];
__device__ float g_att[NN * DD];      // unnormalized attn out
__device__ float g_l[HH * NN];        // row sums
__device__ float g_tmp[NN * DD];
// bucketed edge lists keyed by source row
__device__ int g_cnt[NN];
__device__ int g_bkt[NN * BCAP];      // dst | (type<<12)
__device__ int g_ovf[EE];             // (src<<16) | (type<<12) | dst
__device__ int g_ovfn;
// split-bf16 operands
__device__ __nv_bfloat16 g_qs[HH * NN * 64];   // per row: [hi 32][lo 32], q pre-scaled
__device__ __nv_bfloat16 g_ks[HH * NN * 64];
__device__ __nv_bfloat16 g_vth[HH * 32 * NN];  // V^T hi  [h][d][n]
__device__ __nv_bfloat16 g_vtl[HH * 32 * NN];  // V^T lo
__device__ __nv_bfloat16 g_vs[HH * NN * 32];   // V hi, row-major [h][n][dh] (for k_corr)

// ---------------- flash3 smem layout (dynamic, double-buffered K/V) ----------------
#define OQ    0
#define OKB   18432                 // K bufs: +bi*18432  (128 x 144B)
#define OVB   55296                 // V bufs: +bi*17408; hi at +0, lo at +8704 (32 x 272B)
#define SM3   90112

// ---------------- packed fp32x2 helpers ----------------
#define PACK2(u, lo, hi) asm("mov.b64 %0, {%1,%2};" : "=l"(u) : "f"(lo), "f"(hi))
#define UNPACK2(lo, hi, u) asm("mov.b64 {%0,%1}, %2;" : "=f"(lo), "=f"(hi) : "l"(u))
#define FMA2(d, a, b) asm("fma.rn.f32x2 %0, %1, %2, %0;" : "+l"(d) : "l"(a), "l"(b))

__device__ __forceinline__ uint32_t s2u(const void* p) {
    uint32_t a;
    asm("{ .reg .u64 t; cvta.to.shared.u64 t, %1; cvt.u32.u64 %0, t; }" : "=r"(a) : "l"(p));
    return a;
}

// exp via MUFU pipe (overlaps with FMA + tensor pipes)
__device__ __forceinline__ float mexp(float s) {
    float r;
    asm("ex2.approx.f32 %0, %1;" : "=f"(r) : "f"(s * 1.4426950408889634f));
    return r;
}

#define LDM_X2(r_, a_)                                                         \
    asm volatile("ldmatrix.sync.aligned.m8n8.x2.shared.b16 {%0,%1}, [%2];"     \
                 : "=r"((r_)[0]), "=r"((r_)[1]) : "r"(a_))
#define LDM_X4(r_, a_)                                                         \
    asm volatile("ldmatrix.sync.aligned.m8n8.x4.shared.b16 {%0,%1,%2,%3}, [%4];" \
                 : "=r"((r_)[0]), "=r"((r_)[1]), "=r"((r_)[2]), "=r"((r_)[3]) : "r"(a_))
#define MMA_BF16(c_, a_, b_)                                                   \
    asm volatile("mma.sync.aligned.m16n8k16.row.col.f32.bf16.bf16.f32 "        \
                 "{%0,%1,%2,%3}, {%4,%5,%6,%7}, {%8,%9}, {%0,%1,%2,%3};"       \
                 : "+f"((c_)[0]), "+f"((c_)[1]), "+f"((c_)[2]), "+f"((c_)[3])  \
                 : "r"((a_)[0]), "r"((a_)[1]), "r"((a_)[2]), "r"((a_)[3]),     \
                   "r"((b_)[0]), "r"((b_)[1]))
#define CPA16(dst, src) \
    asm volatile("cp.async.ca.shared.global [%0], [%1], 16;" :: "r"(dst), "l"(src))
#define CPA_COMMIT() asm volatile("cp.async.commit_group;" ::: "memory")
#define CPA_WAIT0() asm volatile("cp.async.wait_group 0;" ::: "memory")
#define CPA_WAIT1() asm volatile("cp.async.wait_group 1;" ::: "memory")

// ---------------- 1. QKV projections (x+pos fused in, split-bf16 fused out) ----------------
__global__ void __launch_bounds__(256) k_qkv(
    const float* __restrict__ x, const float* __restrict__ pos,
    const float* __restrict__ Wq, const float* __restrict__ bq,
    const float* __restrict__ Wk, const float* __restrict__ bk,
    const float* __restrict__ Wv, const float* __restrict__ bv) {
    const int z = blockIdx.z;
    const float* W;
    const float* bias;
    float* out;
    if (z == 0)      { W = Wq; bias = bq; out = g_q; }
    else if (z == 1) { W = Wk; bias = bk; out = g_k; }
    else             { W = Wv; bias = bv; out = g_v; }

    __shared__ __align__(16) float AsT[32][68];   // [k][row]
    __shared__ __align__(16) float Bs2[32][68];   // [k][col]
    const int m0 = blockIdx.y * 64, n0 = blockIdx.x * 64;
    const int tid = threadIdx.x, tx = tid & 15, ty = tid >> 4;

    unsigned long long acc[4][2];
    #pragma unroll
    for (int i = 0; i < 4; i++) { acc[i][0] = 0ull; acc[i][1] = 0ull; }

    for (int kk = 0; kk < DD; kk += 32) {
        #pragma unroll
        for (int i = tid; i < 64 * 32; i += 256) {
            int r = i >> 5, c = i & 31;
            int gi = (m0 + r) * DD + kk + c;
            AsT[c][r] = x[gi] + pos[gi];
        }
        #pragma unroll
        for (int i = tid; i < 32 * 64; i += 256) {
            int r = i >> 6, c = i & 63;
            Bs2[r][c] = W[(kk + r) * DD + n0 + c];
        }
        __syncthreads();
        #pragma unroll 8
        for (int kq = 0; kq < 32; kq++) {
            float4 a = *(const float4*)&AsT[kq][ty * 4];
            ulonglong2 b = *(const ulonglong2*)&Bs2[kq][tx * 4];
            float av[4] = {a.x, a.y, a.z, a.w};
            #pragma unroll
            for (int r = 0; r < 4; r++) {
                unsigned long long ap;
                PACK2(ap, av[r], av[r]);
                FMA2(acc[r][0], ap, b.x);
                FMA2(acc[r][1], ap, b.y);
            }
        }
        __syncthreads();
    }

    __nv_bfloat16* sp = (z == 0) ? g_qs : g_ks;
    const float sc = (z == 0) ? 0.17677669529663687f : 1.0f;
    #pragma unroll
    for (int i = 0; i < 4; i++) {
        int row = m0 + ty * 4 + i;
        float v0, v1, v2, v3;
        UNPACK2(v0, v1, acc[i][0]);
        UNPACK2(v2, v3, acc[i][1]);
        float vv[4] = {v0, v1, v2, v3};
        int col0 = n0 + tx * 4;
        int hh2 = col0 >> 5, dh0 = col0 & 31;
        if (z < 2) {
            #pragma unroll
            for (int j = 0; j < 4; j++) {
                int col = col0 + j;
                float val = vv[j] + bias[col];
                out[((size_t)hh2 * NN + row) * DHH + (col & 31)] = val;
                float sv = val * sc;
                __nv_bfloat16 hi = __float2bfloat16(sv);
                size_t base = ((size_t)hh2 * NN + row) * 64 + (col & 31);
                sp[base] = hi;
                sp[base + 32] = __float2bfloat16(sv - __bfloat162float(hi));
            }
        } else {
            __nv_bfloat16 hv[4];
            #pragma unroll
            for (int j = 0; j < 4; j++) {
                int col = col0 + j;
                float val = vv[j] + bias[col];
                out[((size_t)hh2 * NN + row) * DHH + (col & 31)] = val;
                hv[j] = __float2bfloat16(val);
            }
            *(uint2*)(g_vs + ((size_t)hh2 * NN + row) * 32 + dh0) = *(uint2*)hv;
        }
    }
}

// ---------------- 2. V^T hi/lo split ----------------
__global__ void k_split_vt() {
    int idx = blockIdx.x * 256 + threadIdx.x;     // h*NN+n
    int hh2 = idx >> 12, n = idx & 4095;
    const float* src = g_v + (size_t)idx * 32;
    #pragma unroll
    for (int d = 0; d < 32; d++) {
        float v = src[d];
        __nv_bfloat16 hi = __float2bfloat16(v);
        size_t o = (size_t)(hh2 * 32 + d) * NN + n;
        g_vth[o] = hi;
        g_vtl[o] = __float2bfloat16(v - __bfloat162float(hi));
    }
}

// ---------------- 3. bucketed edge lists (replaces scan+scatter+sort) ----------------
__global__ void k_zero() {
    int i = blockIdx.x * 256 + threadIdx.x;
    if (i < NN) g_cnt[i] = 0;
    if (i == 0) g_ovfn = 0;
}
__global__ void k_bucket(const int* __restrict__ ei, const int* __restrict__ et) {
    int e = blockIdx.x * 256 + threadIdx.x;
    int src = ei[e];
    int pk = ei[EE + e] | (et[e] << 12);
    int pos = atomicAdd(&g_cnt[src], 1);
    if (pos < BCAP) {
        g_bkt[src * BCAP + pos] = pk;
    } else {
        int op = atomicAdd(&g_ovfn, 1);          // correctness fallback (P ~ 1e-23)
        g_ovf[op] = (src << 16) | pk;
    }
}

// ---------------- 4. dense attention via mma.sync, double-buffered cp.async ----------------
// grid (NN/128, HH), 256 threads (8 warps x 16 rows). O and l written unnormalized.
__global__ void __launch_bounds__(256, 2) k_flash3() {
    extern __shared__ char sm[];
    const uint32_t sb = s2u(sm);
    const int tid = threadIdx.x, w = tid >> 5, lane = tid & 31;
    const int h = blockIdx.y, m0 = blockIdx.x * 128;
    const int g = lane >> 2, c = lane & 3;

    // prologue: Q tile (plain stores) + tile 0 K/V via cp.async group 0
    {
        const uint4* qsrc = ((const uint4*)g_qs) + (size_t)(h * NN + m0) * 8;
        for (int t2 = tid; t2 < 1024; t2 += 256) {
            int r = t2 >> 3, u = t2 & 7;
            *(uint4*)(sm + OQ + r * 144 + u * 16) = qsrc[r * 8 + u];
        }
        const char* ksrc = (const char*)(g_ks + (size_t)(h * NN) * 64);
        for (int t2 = tid; t2 < 1024; t2 += 256) {
            int r = t2 >> 3, u = t2 & 7;
            CPA16(sb + OKB + r * 144 + u * 16, ksrc + (size_t)(r * 8 + u) * 16);
        }
        for (int t2 = tid; t2 < 512; t2 += 256) {
            int d = t2 >> 4, u = t2 & 15;
            size_t go = ((size_t)(h * 32 + d) * NN) * 2 + u * 16;
            CPA16(sb + OVB + d * 272 + u * 16, (const char*)g_vth + go);
            CPA16(sb + OVB + 8704 + d * 272 + u * 16, (const char*)g_vtl + go);
        }
        CPA_COMMIT();
        CPA_WAIT0();
    }
    __syncthreads();

    // persistent Q A-fragments: [Qh u0][Qh u1][Ql u0][Ql u1]
    uint32_t qf[4][4];
    {
        int r = (lane & 7) + ((lane >> 3) & 1) * 8;
        uint32_t base = sb + OQ + (w * 16 + r) * 144 + (lane >> 4) * 16;
        #pragma unroll
        for (int s = 0; s < 4; s++) LDM_X4(qf[s], base + s * 32);
    }

    float oacc[4][4];
    #pragma unroll
    for (int d = 0; d < 4; d++)
        #pragma unroll
        for (int i = 0; i < 4; i++) oacc[d][i] = 0.0f;
    float l0 = 0.0f, l1 = 0.0f;

    for (int t = 0; t < 32; t++) {
        __syncthreads();
        if (t + 1 < 32) {
            int jj = (t + 1) * 128, bi = (t + 1) & 1;
            const char* ksrc = (const char*)(g_ks + (size_t)(h * NN + jj) * 64);
            for (int t2 = tid; t2 < 1024; t2 += 256) {
                int r = t2 >> 3, u = t2 & 7;
                CPA16(sb + OKB + bi * 18432 + r * 144 + u * 16, ksrc + (size_t)(r * 8 + u) * 16);
            }
            for (int t2 = tid; t2 < 512; t2 += 256) {
                int d = t2 >> 4, u = t2 & 15;
                size_t go = ((size_t)(h * 32 + d) * NN + jj) * 2 + u * 16;
                CPA16(sb + OVB + bi * 17408 + d * 272 + u * 16, (const char*)g_vth + go);
                CPA16(sb + OVB + bi * 17408 + 8704 + d * 272 + u * 16, (const char*)g_vtl + go);
            }
            CPA_COMMIT();
            CPA_WAIT1();
        } else {
            CPA_WAIT0();
        }
        __syncthreads();

        const int bi = t & 1;
        const uint32_t kbase = sb + OKB + bi * 18432 + (lane & 7) * 144 + ((lane >> 3) & 1) * 16;
        const uint32_t vbh = sb + OVB + bi * 17408 + (lane & 7) * 272 + ((lane >> 3) & 1) * 16;
        const uint32_t vbl = vbh + 8704;

        #pragma unroll 1
        for (int kg = 0; kg < 8; kg++) {
            float sa[4] = {0.f, 0.f, 0.f, 0.f};
            float sbv[4] = {0.f, 0.f, 0.f, 0.f};
            uint32_t b0[2], b1[2];
            uint32_t ka0 = kbase + (2 * kg) * (8 * 144);
            uint32_t ka1 = kbase + (2 * kg + 1) * (8 * 144);
            LDM_X2(b0, ka0);        LDM_X2(b1, ka0 + 32);
            MMA_BF16(sa, qf[0], b0); MMA_BF16(sa, qf[1], b1);
            MMA_BF16(sa, qf[2], b0); MMA_BF16(sa, qf[3], b1);
            LDM_X2(b0, ka0 + 64);   LDM_X2(b1, ka0 + 96);
            MMA_BF16(sa, qf[0], b0); MMA_BF16(sa, qf[1], b1);
            LDM_X2(b0, ka1);        LDM_X2(b1, ka1 + 32);
            MMA_BF16(sbv, qf[0], b0); MMA_BF16(sbv, qf[1], b1);
            MMA_BF16(sbv, qf[2], b0); MMA_BF16(sbv, qf[3], b1);
            LDM_X2(b0, ka1 + 64);   LDM_X2(b1, ka1 + 96);
            MMA_BF16(sbv, qf[0], b0); MMA_BF16(sbv, qf[1], b1);

            // exp on the MUFU pipe (overlaps tensor + FMA work)
            #pragma unroll
            for (int i = 0; i < 4; i++) { sa[i] = mexp(sa[i]); sbv[i] = mexp(sbv[i]); }
            l0 += sa[0] + sa[1] + sbv[0] + sbv[1];
            l1 += sa[2] + sa[3] + sbv[2] + sbv[3];

            // P in bf16 (hi only)
            uint32_t ah[4];
            asm("cvt.rn.bf16x2.f32 %0, %1, %2;" : "=r"(ah[0]) : "f"(sa[1]), "f"(sa[0]));
            asm("cvt.rn.bf16x2.f32 %0, %1, %2;" : "=r"(ah[1]) : "f"(sa[3]), "f"(sa[2]));
            asm("cvt.rn.bf16x2.f32 %0, %1, %2;" : "=r"(ah[2]) : "f"(sbv[1]), "f"(sbv[0]));
            asm("cvt.rn.bf16x2.f32 %0, %1, %2;" : "=r"(ah[3]) : "f"(sbv[3]), "f"(sbv[2]));

            #pragma unroll
            for (int d = 0; d < 4; d++) {
                uint32_t vh[2], vl[2];
                LDM_X2(vh, vbh + d * (8 * 272) + kg * 32);
                LDM_X2(vl, vbl + d * (8 * 272) + kg * 32);
                MMA_BF16(oacc[d], ah, vh);
                MMA_BF16(oacc[d], ah, vl);
            }
        }
    }

    l0 += __shfl_xor_sync(0xffffffffu, l0, 1);
    l0 += __shfl_xor_sync(0xffffffffu, l0, 2);
    l1 += __shfl_xor_sync(0xffffffffu, l1, 1);
    l1 += __shfl_xor_sync(0xffffffffu, l1, 2);
    int row0 = m0 + w * 16 + g;
    if (c == 0) {
        g_l[h * NN + row0] = l0;
        g_l[h * NN + row0 + 8] = l1;
    }
    float* o0 = g_att + (size_t)row0 * DD + h * 32;
    float* o1 = g_att + (size_t)(row0 + 8) * DD + h * 32;
    #pragma unroll
    for (int d = 0; d < 4; d++) {
        *(float2*)(o0 + d * 8 + 2 * c) = make_float2(oacc[d][0], oacc[d][1]);
        *(float2*)(o1 + d * 8 + 2 * c) = make_float2(oacc[d][2], oacc[d][3]);
    }
}

// ---------------- 5. sparse edge-bias correction (per-edge; bf16 K/V) ----------------
__global__ void __launch_bounds__(256) k_corr(const float* __restrict__ emb) {
    int t = blockIdx.x * 256 + threadIdx.x;
    int row = t >> 3, h = t & 7;
    int n = g_cnt[row];
    if (n == 0) return;
    int nb = n < BCAP ? n : BCAP;

    const float* qp = g_q + ((size_t)h * NN + row) * 32;
    float4 qv[8];
    #pragma unroll
    for (int i = 0; i < 8; i++) qv[i] = ((const float4*)qp)[i];
    const __nv_bfloat16* kh_ = g_ks + (size_t)h * NN * 64;   // hi half at row*64
    const __nv_bfloat16* vh_ = g_vs + (size_t)h * NN * 32;

    float4 oa[8];
    #pragma unroll
    for (int i = 0; i < 8; i++) oa[i] = make_float4(0.f, 0.f, 0.f, 0.f);
    float lacc = 0.0f;
    const float scale = 0.17677669529663687f;
    const int* bkt = g_bkt + row * BCAP;

    for (int idx = 0; idx < nb; idx++) {
        int pk = bkt[idx];
        int d = pk & 0xFFF;
        float bs = emb[(pk >> 12) * HH + h];
        const __nv_bfloat162* kp = (const __nv_bfloat162*)(kh_ + (size_t)d * 64);
        float s = 0.0f;
        #pragma unroll
        for (int i = 0; i < 8; i++) {
            float2 a = __bfloat1622float2(kp[2 * i]);
            float2 b = __bfloat1622float2(kp[2 * i + 1]);
            s += qv[i].x * a.x + qv[i].y * a.y + qv[i].z * b.x + qv[i].w * b.y;
        }
        float wgt = __expf(s * scale) * (__expf(bs) - 1.0f);
        lacc += wgt;
        const __nv_bfloat162* vp = (const __nv_bfloat162*)(vh_ + (size_t)d * 32);
        #pragma unroll
        for (int i = 0; i < 8; i++) {
            float2 a = __bfloat1622float2(vp[2 * i]);
            float2 b = __bfloat1622float2(vp[2 * i + 1]);
            oa[i].x += wgt * a.x; oa[i].y += wgt * a.y;
            oa[i].z += wgt * b.x; oa[i].w += wgt * b.y;
        }
    }
    if (n > BCAP) {   // correctness fallback, statistically never taken
        int on = g_ovfn;
        for (int idx = 0; idx < on; idx++) {
            int rec = g_ovf[idx];
            if ((rec >> 16) != row) continue;
            int d = rec & 0xFFF;
            float bs = emb[((rec >> 12) & 0xF) * HH + h];
            const __nv_bfloat162* kp = (const __nv_bfloat162*)(kh_ + (size_t)d * 64);
            float s = 0.0f;
            #pragma unroll
            for (int i = 0; i < 8; i++) {
                float2 a = __bfloat1622float2(kp[2 * i]);
                float2 b = __bfloat1622float2(kp[2 * i + 1]);
                s += qv[i].x * a.x + qv[i].y * a.y + qv[i].z * b.x + qv[i].w * b.y;
            }
            float wgt = __expf(s * scale) * (__expf(bs) - 1.0f);
            lacc += wgt;
            const __nv_bfloat162* vp = (const __nv_bfloat162*)(vh_ + (size_t)d * 32);
            #pragma unroll
            for (int i = 0; i < 8; i++) {
                float2 a = __bfloat1622float2(vp[2 * i]);
                float2 b = __bfloat1622float2(vp[2 * i + 1]);
                oa[i].x += wgt * a.x; oa[i].y += wgt * a.y;
                oa[i].z += wgt * b.x; oa[i].w += wgt * b.y;
            }
        }
    }

    g_l[h * NN + row] += lacc;
    float* dst = g_att + (size_t)row * DD + h * 32;
    #pragma unroll
    for (int i = 0; i < 8; i++) {
        float4 cur = ((float4*)dst)[i];
        ((float4*)dst)[i] = make_float4(cur.x + oa[i].x, cur.y + oa[i].y,
                                        cur.z + oa[i].z, cur.w + oa[i].w);
    }
}

// ---------------- 6. tmp = x + (att/l) @ Wo + bo  (normalization fused) ----------------
__global__ void __launch_bounds__(256) k_oproj(const float* __restrict__ Wo,
                                               const float* __restrict__ bo,
                                               const float* __restrict__ x) {
    __shared__ __align__(16) float AsT[32][68];
    __shared__ __align__(16) float Bs2[32][68];
    __shared__ float invl[64][8];
    const int m0 = blockIdx.y * 64, n0 = blockIdx.x * 64;
    const int tid = threadIdx.x, tx = tid & 15, ty = tid >> 4;

    #pragma unroll
    for (int i = tid; i < 512; i += 256) {
        int r = i >> 3, hh2 = i & 7;
        invl[r][hh2] = 1.0f / g_l[hh2 * NN + m0 + r];
    }
    __syncthreads();

    unsigned long long acc[4][2];
    #pragma unroll
    for (int i = 0; i < 4; i++) { acc[i][0] = 0ull; acc[i][1] = 0ull; }

    for (int kk = 0; kk < DD; kk += 32) {
        #pragma unroll
        for (int i = tid; i < 64 * 32; i += 256) {
            int r = i >> 5, c = i & 31;
            AsT[c][r] = g_att[(m0 + r) * DD + kk + c] * invl[r][(kk + c) >> 5];
        }
        #pragma unroll
        for (int i = tid; i < 32 * 64; i += 256) {
            int r = i >> 6, c = i & 63;
            Bs2[r][c] = Wo[(kk + r) * DD + n0 + c];
        }
        __syncthreads();
        #pragma unroll 8
        for (int kq = 0; kq < 32; kq++) {
            float4 a = *(const float4*)&AsT[kq][ty * 4];
            ulonglong2 b = *(const ulonglong2*)&Bs2[kq][tx * 4];
            float av[4] = {a.x, a.y, a.z, a.w};
            #pragma unroll
            for (int r = 0; r < 4; r++) {
                unsigned long long ap;
                PACK2(ap, av[r], av[r]);
                FMA2(acc[r][0], ap, b.x);
                FMA2(acc[r][1], ap, b.y);
            }
        }
        __syncthreads();
    }
    #pragma unroll
    for (int i = 0; i < 4; i++) {
        int row = m0 + ty * 4 + i;
        float v0, v1, v2, v3;
        UNPACK2(v0, v1, acc[i][0]);
        UNPACK2(v2, v3, acc[i][1]);
        float vv[4] = {v0, v1, v2, v3};
        #pragma unroll
        for (int j = 0; j < 4; j++) {
            int col = n0 + tx * 4 + j;
            g_tmp[(size_t)row * DD + col] = vv[j] + bo[col] + x[(size_t)row * DD + col];
        }
    }
}

// ---------------- 7. LayerNorm ----------------
__global__ void __launch_bounds__(256) k_ln(const float* __restrict__ gamma,
                                            const float* __restrict__ beta,
                                            float* __restrict__ out) {
    const int n = blockIdx.x, tid = threadIdx.x;
    float v = g_tmp[(size_t)n * DD + tid];
    __shared__ float red[8];
    float s = v;
    #pragma unroll
    for (int o = 16; o > 0; o >>= 1) s += __shfl_xor_sync(0xffffffffu, s, o);
    if ((tid & 31) == 0) red[tid >> 5] = s;
    __syncthreads();
    float tot = 0.f;
    #pragma unroll
    for (int i = 0; i < 8; i++) tot += red[i];
    float mu = tot * (1.0f / DD);
    float d = v - mu;
    __syncthreads();
    float sq = d * d;
    #pragma unroll
    for (int o = 16; o > 0; o >>= 1) sq += __shfl_xor_sync(0xffffffffu, sq, o);
    if ((tid & 31) == 0) red[tid >> 5] = sq;
    __syncthreads();
    float tot2 = 0.f;
    #pragma unroll
    for (int i = 0; i < 8; i++) tot2 += red[i];
    float var = tot2 * (1.0f / DD);
    out[(size_t)n * DD + tid] = d * rsqrtf(var + 1e-5f) * gamma[tid] + beta[tid];
}

// ---------------- launch ----------------
extern "C" void kernel_launch(void* const* d_in, const int* in_sizes, int n_in,
                              void* d_out, int out_size) {
    const float* x       = (const float*)d_in[0];
    const float* pos     = (const float*)d_in[1];
    const int* ei        = (const int*)d_in[2];
    const int* et        = (const int*)d_in[3];
    const float* Wq = (const float*)d_in[4];
    const float* bq = (const float*)d_in[5];
    const float* Wk = (const float*)d_in[6];
    const float* bk = (const float*)d_in[7];
    const float* Wv = (const float*)d_in[8];
    const float* bv = (const float*)d_in[9];
    const float* Wo = (const float*)d_in[10];
    const float* bo = (const float*)d_in[11];
    const float* emb   = (const float*)d_in[12];
    const float* gamma = (const float*)d_in[13];
    const float* beta  = (const float*)d_in[14];
    float* out = (float*)d_out;

    cudaFuncSetAttribute(k_flash3, cudaFuncAttributeMaxDynamicSharedMemorySize, SM3);

    k_qkv<<<dim3(DD / 64, NN / 64, 3), 256>>>(x, pos, Wq, bq, Wk, bk, Wv, bv);
    k_split_vt<<<HH * NN / 256, 256>>>();
    k_zero<<<(NN + 255) / 256, 256>>>();
    k_bucket<<<EE / 256, 256>>>(ei, et);
    k_flash3<<<dim3(NN / 128, HH), 256, SM3>>>();
    k_corr<<<(NN * HH) / 256, 256>>>(emb);
    k_oproj<<<dim3(DD / 64, NN / 64), 256>>>(Wo, bo, x);
    k_ln<<<NN, 256>>>(gamma, beta, out);
}

// round 16
// speedup vs baseline: 1.7302x; 1.0661x over previous
#include <cuda_runtime.h>
#include <cuda_bf16.h>
#include <cstdint>

#define NN 4096
#define DD 256
#define HH 8
#define DHH 32
#define EE 131072
#define BCAP 96

// ---------------- scratch ----------------
__device__ float g_q[HH * NN * DHH];
__device__ float g_k[HH * NN * DHH];
__device__ float g_v[HH * NN * DHH];
__device__ float g_att[NN * DD];      // unnormalized attn out
__device__ float g_l[HH * NN];        // row sums
__device__ float g_tmp[NN * DD];
// bucketed edge lists keyed by source row
__device__ int g_cnt[NN];
__device__ int g_bkt[NN * BCAP];      // dst | (type<<12)
__device__ int g_ovf[EE];             // (src<<16) | (type<<12) | dst
__device__ int g_ovfn;
// split-bf16 operands
__device__ __nv_bfloat16 g_qs[HH * NN * 64];   // per row: [hi 32][lo 32], q pre-scaled
__device__ __nv_bfloat16 g_ks[HH * NN * 64];
__device__ __nv_bfloat16 g_vth[HH * 32 * NN];  // V^T hi  [h][d][n]
__device__ __nv_bfloat16 g_vs[HH * NN * 32];   // V hi, row-major [h][n][dh] (for k_corr)

// ---------------- flash3 smem layout (dynamic, double-buffered K/V-hi) ----------------
#define OQ    0
#define OKB   18432                 // K bufs: +bi*18432  (128 x 144B)
#define OVB   55296                 // V-hi bufs: +bi*8704 (32 x 272B)
#define SM3   72704

// ---------------- packed fp32x2 helpers ----------------
#define PACK2(u, lo, hi) asm("mov.b64 %0, {%1,%2};" : "=l"(u) : "f"(lo), "f"(hi))
#define UNPACK2(lo, hi, u) asm("mov.b64 {%0,%1}, %2;" : "=f"(lo), "=f"(hi) : "l"(u))
#define FMA2(d, a, b) asm("fma.rn.f32x2 %0, %1, %2, %0;" : "+l"(d) : "l"(a), "l"(b))

__device__ __forceinline__ uint32_t s2u(const void* p) {
    uint32_t a;
    asm("{ .reg .u64 t; cvta.to.shared.u64 t, %1; cvt.u32.u64 %0, t; }" : "=r"(a) : "l"(p));
    return a;
}

// exp via MUFU pipe (overlaps with FMA + tensor pipes)
__device__ __forceinline__ float mexp(float s) {
    float r;
    asm("ex2.approx.f32 %0, %1;" : "=f"(r) : "f"(s * 1.4426950408889634f));
    return r;
}

#define LDM_X2(r_, a_)                                                         \
    asm volatile("ldmatrix.sync.aligned.m8n8.x2.shared.b16 {%0,%1}, [%2];"     \
                 : "=r"((r_)[0]), "=r"((r_)[1]) : "r"(a_))
#define LDM_X4(r_, a_)                                                         \
    asm volatile("ldmatrix.sync.aligned.m8n8.x4.shared.b16 {%0,%1,%2,%3}, [%4];" \
                 : "=r"((r_)[0]), "=r"((r_)[1]), "=r"((r_)[2]), "=r"((r_)[3]) : "r"(a_))
#define MMA_BF16(c_, a_, b_)                                                   \
    asm volatile("mma.sync.aligned.m16n8k16.row.col.f32.bf16.bf16.f32 "        \
                 "{%0,%1,%2,%3}, {%4,%5,%6,%7}, {%8,%9}, {%0,%1,%2,%3};"       \
                 : "+f"((c_)[0]), "+f"((c_)[1]), "+f"((c_)[2]), "+f"((c_)[3])  \
                 : "r"((a_)[0]), "r"((a_)[1]), "r"((a_)[2]), "r"((a_)[3]),     \
                   "r"((b_)[0]), "r"((b_)[1]))
#define CPA16(dst, src) \
    asm volatile("cp.async.ca.shared.global [%0], [%1], 16;" :: "r"(dst), "l"(src))
#define CPA_COMMIT() asm volatile("cp.async.commit_group;" ::: "memory")
#define CPA_WAIT0() asm volatile("cp.async.wait_group 0;" ::: "memory")
#define CPA_WAIT1() asm volatile("cp.async.wait_group 1;" ::: "memory")

// ---------------- 1. QKV projections (x+pos fused in, split-bf16 fused out) ----------------
__global__ void __launch_bounds__(256) k_qkv(
    const float* __restrict__ x, const float* __restrict__ pos,
    const float* __restrict__ Wq, const float* __restrict__ bq,
    const float* __restrict__ Wk, const float* __restrict__ bk,
    const float* __restrict__ Wv, const float* __restrict__ bv) {
    const int z = blockIdx.z;
    const float* W;
    const float* bias;
    float* out;
    if (z == 0)      { W = Wq; bias = bq; out = g_q; }
    else if (z == 1) { W = Wk; bias = bk; out = g_k; }
    else             { W = Wv; bias = bv; out = g_v; }

    __shared__ __align__(16) float AsT[32][68];   // [k][row]
    __shared__ __align__(16) float Bs2[32][68];   // [k][col]
    const int m0 = blockIdx.y * 64, n0 = blockIdx.x * 64;
    const int tid = threadIdx.x, tx = tid & 15, ty = tid >> 4;

    unsigned long long acc[4][2];
    #pragma unroll
    for (int i = 0; i < 4; i++) { acc[i][0] = 0ull; acc[i][1] = 0ull; }

    for (int kk = 0; kk < DD; kk += 32) {
        #pragma unroll
        for (int i = tid; i < 64 * 32; i += 256) {
            int r = i >> 5, c = i & 31;
            int gi = (m0 + r) * DD + kk + c;
            AsT[c][r] = x[gi] + pos[gi];
        }
        #pragma unroll
        for (int i = tid; i < 32 * 64; i += 256) {
            int r = i >> 6, c = i & 63;
            Bs2[r][c] = W[(kk + r) * DD + n0 + c];
        }
        __syncthreads();
        #pragma unroll 8
        for (int kq = 0; kq < 32; kq++) {
            float4 a = *(const float4*)&AsT[kq][ty * 4];
            ulonglong2 b = *(const ulonglong2*)&Bs2[kq][tx * 4];
            float av[4] = {a.x, a.y, a.z, a.w};
            #pragma unroll
            for (int r = 0; r < 4; r++) {
                unsigned long long ap;
                PACK2(ap, av[r], av[r]);
                FMA2(acc[r][0], ap, b.x);
                FMA2(acc[r][1], ap, b.y);
            }
        }
        __syncthreads();
    }

    __nv_bfloat16* sp = (z == 0) ? g_qs : g_ks;
    const float sc = (z == 0) ? 0.17677669529663687f : 1.0f;
    #pragma unroll
    for (int i = 0; i < 4; i++) {
        int row = m0 + ty * 4 + i;
        float v0, v1, v2, v3;
        UNPACK2(v0, v1, acc[i][0]);
        UNPACK2(v2, v3, acc[i][1]);
        float vv[4] = {v0, v1, v2, v3};
        int col0 = n0 + tx * 4;
        int hh2 = col0 >> 5, dh0 = col0 & 31;
        if (z < 2) {
            #pragma unroll
            for (int j = 0; j < 4; j++) {
                int col = col0 + j;
                float val = vv[j] + bias[col];
                out[((size_t)hh2 * NN + row) * DHH + (col & 31)] = val;
                float sv = val * sc;
                __nv_bfloat16 hi = __float2bfloat16(sv);
                size_t base = ((size_t)hh2 * NN + row) * 64 + (col & 31);
                sp[base] = hi;
                sp[base + 32] = __float2bfloat16(sv - __bfloat162float(hi));
            }
        } else {
            __nv_bfloat16 hv[4];
            #pragma unroll
            for (int j = 0; j < 4; j++) {
                int col = col0 + j;
                float val = vv[j] + bias[col];
                out[((size_t)hh2 * NN + row) * DHH + (col & 31)] = val;
                hv[j] = __float2bfloat16(val);
            }
            *(uint2*)(g_vs + ((size_t)hh2 * NN + row) * 32 + dh0) = *(uint2*)hv;
        }
    }
}

// ---------------- 2. V^T hi split ----------------
__global__ void k_split_vt() {
    int idx = blockIdx.x * 256 + threadIdx.x;     // h*NN+n
    int hh2 = idx >> 12, n = idx & 4095;
    const float* src = g_v + (size_t)idx * 32;
    #pragma unroll
    for (int d = 0; d < 32; d++) {
        g_vth[(size_t)(hh2 * 32 + d) * NN + n] = __float2bfloat16(src[d]);
    }
}

// ---------------- 3. bucketed edge lists ----------------
__global__ void k_zero() {
    int i = blockIdx.x * 256 + threadIdx.x;
    if (i < NN) g_cnt[i] = 0;
    if (i == 0) g_ovfn = 0;
}
__global__ void k_bucket(const int* __restrict__ ei, const int* __restrict__ et) {
    int e = blockIdx.x * 256 + threadIdx.x;
    int src = ei[e];
    int pk = ei[EE + e] | (et[e] << 12);
    int pos = atomicAdd(&g_cnt[src], 1);
    if (pos < BCAP) {
        g_bkt[src * BCAP + pos] = pk;
    } else {
        int op = atomicAdd(&g_ovfn, 1);          // correctness fallback (P ~ 1e-23)
        g_ovf[op] = (src << 16) | pk;
    }
}

// ---------------- 4. dense attention via mma.sync, double-buffered cp.async ----------------
// grid (NN/128, HH), 256 threads (8 warps x 16 rows). O and l written unnormalized.
__global__ void __launch_bounds__(256, 2) k_flash3() {
    extern __shared__ char sm[];
    const uint32_t sb = s2u(sm);
    const int tid = threadIdx.x, w = tid >> 5, lane = tid & 31;
    const int h = blockIdx.y, m0 = blockIdx.x * 128;
    const int g = lane >> 2, c = lane & 3;

    // prologue: Q tile (plain stores) + tile 0 K/V via cp.async group 0
    {
        const uint4* qsrc = ((const uint4*)g_qs) + (size_t)(h * NN + m0) * 8;
        for (int t2 = tid; t2 < 1024; t2 += 256) {
            int r = t2 >> 3, u = t2 & 7;
            *(uint4*)(sm + OQ + r * 144 + u * 16) = qsrc[r * 8 + u];
        }
        const char* ksrc = (const char*)(g_ks + (size_t)(h * NN) * 64);
        for (int t2 = tid; t2 < 1024; t2 += 256) {
            int r = t2 >> 3, u = t2 & 7;
            CPA16(sb + OKB + r * 144 + u * 16, ksrc + (size_t)(r * 8 + u) * 16);
        }
        for (int t2 = tid; t2 < 512; t2 += 256) {
            int d = t2 >> 4, u = t2 & 15;
            size_t go = ((size_t)(h * 32 + d) * NN) * 2 + u * 16;
            CPA16(sb + OVB + d * 272 + u * 16, (const char*)g_vth + go);
        }
        CPA_COMMIT();
        CPA_WAIT0();
    }
    __syncthreads();

    // persistent Q A-fragments: [Qh u0][Qh u1][Ql u0][Ql u1]
    uint32_t qf[4][4];
    {
        int r = (lane & 7) + ((lane >> 3) & 1) * 8;
        uint32_t base = sb + OQ + (w * 16 + r) * 144 + (lane >> 4) * 16;
        #pragma unroll
        for (int s = 0; s < 4; s++) LDM_X4(qf[s], base + s * 32);
    }

    float oacc[4][4];
    #pragma unroll
    for (int d = 0; d < 4; d++)
        #pragma unroll
        for (int i = 0; i < 4; i++) oacc[d][i] = 0.0f;
    float l0 = 0.0f, l1 = 0.0f;

    for (int t = 0; t < 32; t++) {
        __syncthreads();
        if (t + 1 < 32) {
            int jj = (t + 1) * 128, bi = (t + 1) & 1;
            const char* ksrc = (const char*)(g_ks + (size_t)(h * NN + jj) * 64);
            for (int t2 = tid; t2 < 1024; t2 += 256) {
                int r = t2 >> 3, u = t2 & 7;
                CPA16(sb + OKB + bi * 18432 + r * 144 + u * 16, ksrc + (size_t)(r * 8 + u) * 16);
            }
            for (int t2 = tid; t2 < 512; t2 += 256) {
                int d = t2 >> 4, u = t2 & 15;
                size_t go = ((size_t)(h * 32 + d) * NN + jj) * 2 + u * 16;
                CPA16(sb + OVB + bi * 8704 + d * 272 + u * 16, (const char*)g_vth + go);
            }
            CPA_COMMIT();
            CPA_WAIT1();
        } else {
            CPA_WAIT0();
        }
        __syncthreads();

        const int bi = t & 1;
        const uint32_t kbase = sb + OKB + bi * 18432 + (lane & 7) * 144 + ((lane >> 3) & 1) * 16;
        const uint32_t vbh = sb + OVB + bi * 8704 + (lane & 7) * 272 + ((lane >> 3) & 1) * 16;

        #pragma unroll 1
        for (int kg = 0; kg < 8; kg++) {
            float sa[4] = {0.f, 0.f, 0.f, 0.f};
            float sbv[4] = {0.f, 0.f, 0.f, 0.f};
            uint32_t b0[2], b1[2];
            uint32_t ka0 = kbase + (2 * kg) * (8 * 144);
            uint32_t ka1 = kbase + (2 * kg + 1) * (8 * 144);
            LDM_X2(b0, ka0);        LDM_X2(b1, ka0 + 32);
            MMA_BF16(sa, qf[0], b0); MMA_BF16(sa, qf[1], b1);
            MMA_BF16(sa, qf[2], b0); MMA_BF16(sa, qf[3], b1);
            LDM_X2(b0, ka0 + 64);   LDM_X2(b1, ka0 + 96);
            MMA_BF16(sa, qf[0], b0); MMA_BF16(sa, qf[1], b1);
            LDM_X2(b0, ka1);        LDM_X2(b1, ka1 + 32);
            MMA_BF16(sbv, qf[0], b0); MMA_BF16(sbv, qf[1], b1);
            MMA_BF16(sbv, qf[2], b0); MMA_BF16(sbv, qf[3], b1);
            LDM_X2(b0, ka1 + 64);   LDM_X2(b1, ka1 + 96);
            MMA_BF16(sbv, qf[0], b0); MMA_BF16(sbv, qf[1], b1);

            // exp on the MUFU pipe (overlaps tensor + FMA work)
            #pragma unroll
            for (int i = 0; i < 4; i++) { sa[i] = mexp(sa[i]); sbv[i] = mexp(sbv[i]); }
            l0 += sa[0] + sa[1] + sbv[0] + sbv[1];
            l1 += sa[2] + sa[3] + sbv[2] + sbv[3];

            // P in bf16 (hi only)
            uint32_t ah[4];
            asm("cvt.rn.bf16x2.f32 %0, %1, %2;" : "=r"(ah[0]) : "f"(sa[1]), "f"(sa[0]));
            asm("cvt.rn.bf16x2.f32 %0, %1, %2;" : "=r"(ah[1]) : "f"(sa[3]), "f"(sa[2]));
            asm("cvt.rn.bf16x2.f32 %0, %1, %2;" : "=r"(ah[2]) : "f"(sbv[1]), "f"(sbv[0]));
            asm("cvt.rn.bf16x2.f32 %0, %1, %2;" : "=r"(ah[3]) : "f"(sbv[3]), "f"(sbv[2]));

            // O += P * V-hi (V-lo dropped: same order as P's own bf16 rounding)
            #pragma unroll
            for (int d = 0; d < 4; d++) {
                uint32_t vh[2];
                LDM_X2(vh, vbh + d * (8 * 272) + kg * 32);
                MMA_BF16(oacc[d], ah, vh);
            }
        }
    }

    l0 += __shfl_xor_sync(0xffffffffu, l0, 1);
    l0 += __shfl_xor_sync(0xffffffffu, l0, 2);
    l1 += __shfl_xor_sync(0xffffffffu, l1, 1);
    l1 += __shfl_xor_sync(0xffffffffu, l1, 2);
    int row0 = m0 + w * 16 + g;
    if (c == 0) {
        g_l[h * NN + row0] = l0;
        g_l[h * NN + row0 + 8] = l1;
    }
    float* o0 = g_att + (size_t)row0 * DD + h * 32;
    float* o1 = g_att + (size_t)(row0 + 8) * DD + h * 32;
    #pragma unroll
    for (int d = 0; d < 4; d++) {
        *(float2*)(o0 + d * 8 + 2 * c) = make_float2(oacc[d][0], oacc[d][1]);
        *(float2*)(o1 + d * 8 + 2 * c) = make_float2(oacc[d][2], oacc[d][3]);
    }
}

// ---------------- 5. sparse edge-bias correction (per-edge; bf16 K/V) ----------------
__global__ void __launch_bounds__(256) k_corr(const float* __restrict__ emb) {
    int t = blockIdx.x * 256 + threadIdx.x;
    int row = t >> 3, h = t & 7;
    int n = g_cnt[row];
    if (n == 0) return;
    int nb = n < BCAP ? n : BCAP;

    const float* qp = g_q + ((size_t)h * NN + row) * 32;
    float4 qv[8];
    #pragma unroll
    for (int i = 0; i < 8; i++) qv[i] = ((const float4*)qp)[i];
    const __nv_bfloat16* kh_ = g_ks + (size_t)h * NN * 64;   // hi half at row*64
    const __nv_bfloat16* vh_ = g_vs + (size_t)h * NN * 32;

    float4 oa[8];
    #pragma unroll
    for (int i = 0; i < 8; i++) oa[i] = make_float4(0.f, 0.f, 0.f, 0.f);
    float lacc = 0.0f;
    const float scale = 0.17677669529663687f;
    const int* bkt = g_bkt + row * BCAP;

    for (int idx = 0; idx < nb; idx++) {
        int pk = bkt[idx];
        int d = pk & 0xFFF;
        float bs = emb[(pk >> 12) * HH + h];
        const __nv_bfloat162* kp = (const __nv_bfloat162*)(kh_ + (size_t)d * 64);
        float s = 0.0f;
        #pragma unroll
        for (int i = 0; i < 8; i++) {
            float2 a = __bfloat1622float2(kp[2 * i]);
            float2 b = __bfloat1622float2(kp[2 * i + 1]);
            s += qv[i].x * a.x + qv[i].y * a.y + qv[i].z * b.x + qv[i].w * b.y;
        }
        float wgt = __expf(s * scale) * (__expf(bs) - 1.0f);
        lacc += wgt;
        const __nv_bfloat162* vp = (const __nv_bfloat162*)(vh_ + (size_t)d * 32);
        #pragma unroll
        for (int i = 0; i < 8; i++) {
            float2 a = __bfloat1622float2(vp[2 * i]);
            float2 b = __bfloat1622float2(vp[2 * i + 1]);
            oa[i].x += wgt * a.x; oa[i].y += wgt * a.y;
            oa[i].z += wgt * b.x; oa[i].w += wgt * b.y;
        }
    }
    if (n > BCAP) {   // correctness fallback, statistically never taken
        int on = g_ovfn;
        for (int idx = 0; idx < on; idx++) {
            int rec = g_ovf[idx];
            if ((rec >> 16) != row) continue;
            int d = rec & 0xFFF;
            float bs = emb[((rec >> 12) & 0xF) * HH + h];
            const __nv_bfloat162* kp = (const __nv_bfloat162*)(kh_ + (size_t)d * 64);
            float s = 0.0f;
            #pragma unroll
            for (int i = 0; i < 8; i++) {
                float2 a = __bfloat1622float2(kp[2 * i]);
                float2 b = __bfloat1622float2(kp[2 * i + 1]);
                s += qv[i].x * a.x + qv[i].y * a.y + qv[i].z * b.x + qv[i].w * b.y;
            }
            float wgt = __expf(s * scale) * (__expf(bs) - 1.0f);
            lacc += wgt;
            const __nv_bfloat162* vp = (const __nv_bfloat162*)(vh_ + (size_t)d * 32);
            #pragma unroll
            for (int i = 0; i < 8; i++) {
                float2 a = __bfloat1622float2(vp[2 * i]);
                float2 b = __bfloat1622float2(vp[2 * i + 1]);
                oa[i].x += wgt * a.x; oa[i].y += wgt * a.y;
                oa[i].z += wgt * b.x; oa[i].w += wgt * b.y;
            }
        }
    }

    g_l[h * NN + row] += lacc;
    float* dst = g_att + (size_t)row * DD + h * 32;
    #pragma unroll
    for (int i = 0; i < 8; i++) {
        float4 cur = ((float4*)dst)[i];
        ((float4*)dst)[i] = make_float4(cur.x + oa[i].x, cur.y + oa[i].y,
                                        cur.z + oa[i].z, cur.w + oa[i].w);
    }
}

// ---------------- 6. tmp = x + (att/l) @ Wo + bo  (normalization fused) ----------------
__global__ void __launch_bounds__(256) k_oproj(const float* __restrict__ Wo,
                                               const float* __restrict__ bo,
                                               const float* __restrict__ x) {
    __shared__ __align__(16) float AsT[32][68];
    __shared__ __align__(16) float Bs2[32][68];
    __shared__ float invl[64][8];
    const int m0 = blockIdx.y * 64, n0 = blockIdx.x * 64;
    const int tid = threadIdx.x, tx = tid & 15, ty = tid >> 4;

    #pragma unroll
    for (int i = tid; i < 512; i += 256) {
        int r = i >> 3, hh2 = i & 7;
        invl[r][hh2] = 1.0f / g_l[hh2 * NN + m0 + r];
    }
    __syncthreads();

    unsigned long long acc[4][2];
    #pragma unroll
    for (int i = 0; i < 4; i++) { acc[i][0] = 0ull; acc[i][1] = 0ull; }

    for (int kk = 0; kk < DD; kk += 32) {
        #pragma unroll
        for (int i = tid; i < 64 * 32; i += 256) {
            int r = i >> 5, c = i & 31;
            AsT[c][r] = g_att[(m0 + r) * DD + kk + c] * invl[r][(kk + c) >> 5];
        }
        #pragma unroll
        for (int i = tid; i < 32 * 64; i += 256) {
            int r = i >> 6, c = i & 63;
            Bs2[r][c] = Wo[(kk + r) * DD + n0 + c];
        }
        __syncthreads();
        #pragma unroll 8
        for (int kq = 0; kq < 32; kq++) {
            float4 a = *(const float4*)&AsT[kq][ty * 4];
            ulonglong2 b = *(const ulonglong2*)&Bs2[kq][tx * 4];
            float av[4] = {a.x, a.y, a.z, a.w};
            #pragma unroll
            for (int r = 0; r < 4; r++) {
                unsigned long long ap;
                PACK2(ap, av[r], av[r]);
                FMA2(acc[r][0], ap, b.x);
                FMA2(acc[r][1], ap, b.y);
            }
        }
        __syncthreads();
    }
    #pragma unroll
    for (int i = 0; i < 4; i++) {
        int row = m0 + ty * 4 + i;
        float v0, v1, v2, v3;
        UNPACK2(v0, v1, acc[i][0]);
        UNPACK2(v2, v3, acc[i][1]);
        float vv[4] = {v0, v1, v2, v3};
        #pragma unroll
        for (int j = 0; j < 4; j++) {
            int col = n0 + tx * 4 + j;
            g_tmp[(size_t)row * DD + col] = vv[j] + bo[col] + x[(size_t)row * DD + col];
        }
    }
}

// ---------------- 7. LayerNorm ----------------
__global__ void __launch_bounds__(256) k_ln(const float* __restrict__ gamma,
                                            const float* __restrict__ beta,
                                            float* __restrict__ out) {
    const int n = blockIdx.x, tid = threadIdx.x;
    float v = g_tmp[(size_t)n * DD + tid];
    __shared__ float red[8];
    float s = v;
    #pragma unroll
    for (int o = 16; o > 0; o >>= 1) s += __shfl_xor_sync(0xffffffffu, s, o);
    if ((tid & 31) == 0) red[tid >> 5] = s;
    __syncthreads();
    float tot = 0.f;
    #pragma unroll
    for (int i = 0; i < 8; i++) tot += red[i];
    float mu = tot * (1.0f / DD);
    float d = v - mu;
    __syncthreads();
    float sq = d * d;
    #pragma unroll
    for (int o = 16; o > 0; o >>= 1) sq += __shfl_xor_sync(0xffffffffu, sq, o);
    if ((tid & 31) == 0) red[tid >> 5] = sq;
    __syncthreads();
    float tot2 = 0.f;
    #pragma unroll
    for (int i = 0; i < 8; i++) tot2 += red[i];
    float var = tot2 * (1.0f / DD);
    out[(size_t)n * DD + tid] = d * rsqrtf(var + 1e-5f) * gamma[tid] + beta[tid];
}

// ---------------- launch ----------------
extern "C" void kernel_launch(void* const* d_in, const int* in_sizes, int n_in,
                              void* d_out, int out_size) {
    const float* x       = (const float*)d_in[0];
    const float* pos     = (const float*)d_in[1];
    const int* ei        = (const int*)d_in[2];
    const int* et        = (const int*)d_in[3];
    const float* Wq = (const float*)d_in[4];
    const float* bq = (const float*)d_in[5];
    const float* Wk = (const float*)d_in[6];
    const float* bk = (const float*)d_in[7];
    const float* Wv = (const float*)d_in[8];
    const float* bv = (const float*)d_in[9];
    const float* Wo = (const float*)d_in[10];
    const float* bo = (const float*)d_in[11];
    const float* emb   = (const float*)d_in[12];
    const float* gamma = (const float*)d_in[13];
    const float* beta  = (const float*)d_in[14];
    float* out = (float*)d_out;

    cudaFuncSetAttribute(k_flash3, cudaFuncAttributeMaxDynamicSharedMemorySize, SM3);

    k_qkv<<<dim3(DD / 64, NN / 64, 3), 256>>>(x, pos, Wq, bq, Wk, bk, Wv, bv);
    k_split_vt<<<HH * NN / 256, 256>>>();
    k_zero<<<(NN + 255) / 256, 256>>>();
    k_bucket<<<EE / 256, 256>>>(ei, et);
    k_flash3<<<dim3(NN / 128, HH), 256, SM3>>>();
    k_corr<<<(NN * HH) / 256, 256>>>(emb);
    k_oproj<<<dim3(DD / 64, NN / 64), 256>>>(Wo, bo, x);
    k_ln<<<NN, 256>>>(gamma, beta, out);
}